// round 3
// baseline (speedup 1.0000x reference)
#include <cuda_runtime.h>
#include <cstdint>

#define HD   128
#define HD2  256
#define NMAX 100000
#define NG   512
#define EPS  1e-5f

// ---------------- scratch (static device globals; no allocs) ----------------
__device__ float g_h[(size_t)NMAX * HD];      // gather source h
__device__ float g_agg[(size_t)NMAX * HD];    // initialized to h; becomes z = h + sum
__device__ float g_t1[(size_t)NMAX * HD2];    // GEMM1 raw output
__device__ float g_t2[(size_t)NMAX * HD];     // GEMM2 raw output
__device__ float g_feats[(size_t)NMAX * HD];  // layer output feats
__device__ float g_vf[NG * HD];
__device__ float g_vz[NG * HD];
__device__ float g_vt1[NG * HD2];
__device__ float g_vt2[NG * HD];
__device__ float g_pool[NG * HD];
__device__ float g_cnt[NG];
__device__ float g_sum[HD2];
__device__ float g_sumsq[HD2];
__device__ float g_bnA[HD2];
__device__ float g_bnC[HD2];

__device__ __forceinline__ void red_add_v4(float* p, float4 v) {
    asm volatile("red.global.add.v4.f32 [%0], {%1, %2, %3, %4};"
                 :: "l"(p), "f"(v.x), "f"(v.y), "f"(v.z), "f"(v.w)
                 : "memory");
}

// ---------------- kernels ----------------

__global__ void k_init_vf(const float* __restrict__ vn_emb) {
    int i = blockIdx.x * blockDim.x + threadIdx.x;
    if (i < NG * HD) g_vf[i] = vn_emb[i & (HD - 1)];
}

// h = feats_in (+ vf[batch]); agg = h (so scatter yields z = h + sum directly)
__global__ void k_compute_h(const float* __restrict__ feats_in,
                            const int* __restrict__ batch,
                            int useVN, int N) {
    int idx = blockIdx.x * blockDim.x + threadIdx.x;   // float4 index
    int total = N * (HD / 4);
    if (idx >= total) return;
    int row = idx >> 5;            // HD/4 = 32
    int c4  = (idx & 31) << 2;
    float4 v = *(const float4*)&feats_in[(size_t)row * HD + c4];
    if (useVN) {
        int g = batch[row];
        float4 u = *(const float4*)&g_vf[g * HD + c4];
        v.x += u.x; v.y += u.y; v.z += u.z; v.w += u.w;
    }
    *(float4*)&g_h[(size_t)row * HD + c4] = v;
    *(float4*)&g_agg[(size_t)row * HD + c4] = v;
}

// one warp per edge: agg[dst] += h[src]  (vector red, 1 instr per lane)
__global__ void k_scatter(const int* __restrict__ ei, int E) {
    int warp = (blockIdx.x * blockDim.x + threadIdx.x) >> 5;
    int lane = threadIdx.x & 31;
    if (warp >= E) return;
    int s = ei[warp];
    int d = ei[(size_t)E + warp];
    float4 v = *(const float4*)&g_h[(size_t)s * HD + lane * 4];
    red_add_v4(&g_agg[(size_t)d * HD + lane * 4], v);
}

// --------- tiled SGEMM: C[M,N] = act(A)[M,K] @ B[K,N] + bias ---------
// bnOnA: apply y = max(bnA[k]*a + bnC[k], 0) to A elements while staging.
#define BM 128
#define BN 128
#define BK 16
__global__ __launch_bounds__(256) void sgemm_bias(
    const float* __restrict__ A, const float* __restrict__ B,
    const float* __restrict__ bias, float* __restrict__ C,
    int M, int N, int K, int bnOnA)
{
    __shared__ float As[BK][BM + 4];
    __shared__ float Bs[BK][BN];
    int tid = threadIdx.x;
    int bRow = blockIdx.x * BM;
    int bCol = blockIdx.y * BN;
    int tx = tid & 15, ty = tid >> 4;
    float acc[8][8];
#pragma unroll
    for (int i = 0; i < 8; i++)
#pragma unroll
        for (int j = 0; j < 8; j++) acc[i][j] = 0.f;

    for (int k0 = 0; k0 < K; k0 += BK) {
#pragma unroll
        for (int j = 0; j < 2; j++) {
            int slot = tid + j * 256;
            int ar = slot >> 2;
            int ac = (slot & 3) * 4;
            int grow = bRow + ar;
            float4 v = (grow < M) ? *(const float4*)&A[(size_t)grow * K + k0 + ac]
                                  : make_float4(0.f, 0.f, 0.f, 0.f);
            if (bnOnA) {
                float4 a = *(const float4*)&g_bnA[k0 + ac];
                float4 c = *(const float4*)&g_bnC[k0 + ac];
                v.x = fmaxf(fmaf(v.x, a.x, c.x), 0.f);
                v.y = fmaxf(fmaf(v.y, a.y, c.y), 0.f);
                v.z = fmaxf(fmaf(v.z, a.z, c.z), 0.f);
                v.w = fmaxf(fmaf(v.w, a.w, c.w), 0.f);
            }
            As[ac + 0][ar] = v.x; As[ac + 1][ar] = v.y;
            As[ac + 2][ar] = v.z; As[ac + 3][ar] = v.w;
        }
#pragma unroll
        for (int j = 0; j < 2; j++) {
            int slot = tid + j * 256;
            int br = slot >> 5;
            int bc = (slot & 31) * 4;
            *(float4*)&Bs[br][bc] = *(const float4*)&B[(size_t)(k0 + br) * N + bCol + bc];
        }
        __syncthreads();
#pragma unroll
        for (int k = 0; k < BK; k++) {
            float a[8], b[8];
#pragma unroll
            for (int i = 0; i < 8; i++) a[i] = As[k][ty * 8 + i];
#pragma unroll
            for (int i = 0; i < 8; i++) b[i] = Bs[k][tx * 8 + i];
#pragma unroll
            for (int i = 0; i < 8; i++)
#pragma unroll
                for (int j = 0; j < 8; j++)
                    acc[i][j] = fmaf(a[i], b[j], acc[i][j]);
        }
        __syncthreads();
    }
#pragma unroll
    for (int i = 0; i < 8; i++) {
        int grow = bRow + ty * 8 + i;
        if (grow >= M) continue;
#pragma unroll
        for (int j = 0; j < 8; j += 4) {
            int gcol = bCol + tx * 8 + j;
            float4 bv = *(const float4*)&bias[gcol];
            float4 o;
            o.x = acc[i][j + 0] + bv.x;
            o.y = acc[i][j + 1] + bv.y;
            o.z = acc[i][j + 2] + bv.z;
            o.w = acc[i][j + 3] + bv.w;
            *(float4*)&C[(size_t)grow * N + gcol] = o;
        }
    }
}

__global__ void k_zero_stats() {
    int t = threadIdx.x;
    g_sum[t] = 0.f;
    g_sumsq[t] = 0.f;
}

// per-column sum & sumsq over rows; blockDim = 256
__global__ void k_colstats(const float* __restrict__ X, int M, int C) {
    int tid = threadIdx.x;
    int col = tid % C;
    int rsub = tid / C;
    int rowsPerIter = 256 / C;
    float s = 0.f, ss = 0.f;
    for (int r = blockIdx.x * rowsPerIter + rsub; r < M; r += gridDim.x * rowsPerIter) {
        float v = X[(size_t)r * C + col];
        s += v; ss += v * v;
    }
    atomicAdd(&g_sum[col], s);
    atomicAdd(&g_sumsq[col], ss);
}

__global__ void k_finalize(const float* __restrict__ gamma,
                           const float* __restrict__ beta,
                           int C, float invM) {
    int t = threadIdx.x;
    if (t >= C) return;
    float mean = g_sum[t] * invM;
    float var = g_sumsq[t] * invM - mean * mean;
    float r = rsqrtf(var + EPS);
    float a = gamma[t] * r;
    g_bnA[t] = a;
    g_bnC[t] = beta[t] - mean * a;
}

// y = act(x*a + c); write to dst1 (and optionally dst2)
__global__ void k_bn_act(const float* __restrict__ X, int M, int C, int doRelu,
                         float* __restrict__ dst1, float* __restrict__ dst2) {
    int idx = blockIdx.x * blockDim.x + threadIdx.x;   // float4 index
    int total = M * C / 4;
    if (idx >= total) return;
    size_t off = (size_t)idx * 4;
    int col = (int)(off % C);
    float4 v = *(const float4*)&X[off];
    float4 a = *(const float4*)&g_bnA[col];
    float4 c = *(const float4*)&g_bnC[col];
    float4 y;
    y.x = fmaf(v.x, a.x, c.x);
    y.y = fmaf(v.y, a.y, c.y);
    y.z = fmaf(v.z, a.z, c.z);
    y.w = fmaf(v.w, a.w, c.w);
    if (doRelu) {
        y.x = fmaxf(y.x, 0.f); y.y = fmaxf(y.y, 0.f);
        y.z = fmaxf(y.z, 0.f); y.w = fmaxf(y.w, 0.f);
    }
    *(float4*)&dst1[off] = y;
    if (dst2) *(float4*)&dst2[off] = y;
}

__global__ void k_zero_pool() {
    int i = blockIdx.x * blockDim.x + threadIdx.x;
    if (i < NG * HD) g_pool[i] = 0.f;
    if (i < NG) g_cnt[i] = 0.f;
}

// one warp per node: pool[batch[n]] += X[n]; counts
__global__ void k_pool_scatter(const float* __restrict__ X,
                               const int* __restrict__ batch,
                               int addCounts, int N) {
    int warp = (blockIdx.x * blockDim.x + threadIdx.x) >> 5;
    int lane = threadIdx.x & 31;
    if (warp >= N) return;
    int g = batch[warp];
    float4 v = *(const float4*)&X[(size_t)warp * HD + lane * 4];
    red_add_v4(&g_pool[g * HD + lane * 4], v);
    if (addCounts && lane == 0) atomicAdd(&g_cnt[g], 1.f);
}

__global__ void k_vz() {
    int i = blockIdx.x * blockDim.x + threadIdx.x;
    if (i < NG * HD) g_vz[i] = g_pool[i] + g_vf[i];
}

__global__ void k_readout(float* __restrict__ out) {
    int i = blockIdx.x * blockDim.x + threadIdx.x;
    if (i < NG * HD) out[i] = g_pool[i] / fmaxf(g_cnt[i >> 7], 1.f);
}

__global__ void k_copy_vf(float* __restrict__ out) {
    int i = blockIdx.x * blockDim.x + threadIdx.x;
    if (i < NG * HD) out[i] = g_vf[i];
}

// ---------------- host ----------------
extern "C" void kernel_launch(void* const* d_in, const int* in_sizes, int n_in,
                              void* d_out, int out_size) {
    const float* x = (const float*)d_in[0];
    const int* ei = (const int*)d_in[1];      // int32 (JAX x64 disabled)
    const int* batch = (const int*)d_in[2];   // int32
    int base = 3;
    if (n_in > 3 && in_sizes[3] <= 2) base = 4;  // num_graphs scalar present
    const float* conv_w1 = (const float*)d_in[base + 0];
    const float* conv_b1 = (const float*)d_in[base + 1];
    const float* conv_bn_g = (const float*)d_in[base + 2];
    const float* conv_bn_b = (const float*)d_in[base + 3];
    const float* conv_w2 = (const float*)d_in[base + 4];
    const float* conv_b2 = (const float*)d_in[base + 5];
    const float* bn_g = (const float*)d_in[base + 6];
    const float* bn_b = (const float*)d_in[base + 7];
    const float* vn_emb = (const float*)d_in[base + 8];
    const float* vw1 = (const float*)d_in[base + 9];
    const float* vb1 = (const float*)d_in[base + 10];
    const float* vbn1g = (const float*)d_in[base + 11];
    const float* vbn1b = (const float*)d_in[base + 12];
    const float* vw2 = (const float*)d_in[base + 13];
    const float* vb2 = (const float*)d_in[base + 14];
    const float* vbn2g = (const float*)d_in[base + 15];
    const float* vbn2b = (const float*)d_in[base + 16];

    int N = in_sizes[0] / HD;
    int E = in_sizes[1] / 2;
    float* out = (float*)d_out;

    float *p_agg, *p_t1, *p_t2, *p_feats, *p_vz, *p_vt1, *p_vt2, *p_vf;
    cudaGetSymbolAddress((void**)&p_agg, g_agg);
    cudaGetSymbolAddress((void**)&p_t1, g_t1);
    cudaGetSymbolAddress((void**)&p_t2, g_t2);
    cudaGetSymbolAddress((void**)&p_feats, g_feats);
    cudaGetSymbolAddress((void**)&p_vz, g_vz);
    cudaGetSymbolAddress((void**)&p_vt1, g_vt1);
    cudaGetSymbolAddress((void**)&p_vt2, g_vt2);
    cudaGetSymbolAddress((void**)&p_vf, g_vf);

    int gN4 = (N * (HD / 4) + 255) / 256;        // elementwise over [N,HD]
    int gE = (E * 32 + 255) / 256;               // warp per edge
    int gNw = (N * 32 + 255) / 256;              // warp per node
    int gG = (NG * HD + 255) / 256;

    k_init_vf<<<gG, 256>>>(vn_emb);

    for (int i = 0; i < 3; i++) {
        const float* fin = (i == 0) ? x : p_feats;
        k_compute_h<<<gN4, 256>>>(fin, batch, i > 0 ? 1 : 0, N);
        k_scatter<<<gE, 256>>>(ei, E);     // g_agg becomes z = h + sum

        // GEMM1 (z @ w1 + b1) -> t1 raw, then BN stats on t1
        dim3 g1((N + BM - 1) / BM, HD2 / BN);
        sgemm_bias<<<g1, 256>>>(p_agg, conv_w1 + (size_t)i * HD * HD2,
                                conv_b1 + i * HD2, p_t1, N, HD2, HD, 0);
        k_zero_stats<<<1, 256>>>();
        k_colstats<<<512, 256>>>(p_t1, N, HD2);
        k_finalize<<<1, HD2>>>(conv_bn_g + i * HD2, conv_bn_b + i * HD2, HD2, 1.0f / N);

        // GEMM2 with BN+ReLU fused on A load -> t2 raw
        dim3 g2((N + BM - 1) / BM, HD / BN);
        sgemm_bias<<<g2, 256>>>(p_t1, conv_w2 + (size_t)i * HD2 * HD,
                                conv_b2 + i * HD, p_t2, N, HD, HD2, 1);
        k_zero_stats<<<1, 256>>>();
        k_colstats<<<512, 256>>>(p_t2, N, HD);
        k_finalize<<<1, HD>>>(bn_g + i * HD, bn_b + i * HD, HD, 1.0f / N);
        k_bn_act<<<gN4, 256>>>(p_t2, N, HD, (i < 2) ? 1 : 0, p_feats,
                               (i == 2) ? out : nullptr);

        // virtual node update (only i == 1 for L=3)
        if (i == 1) {
            k_zero_pool<<<gG, 256>>>();
            k_pool_scatter<<<gNw, 256>>>(p_feats, batch, 0, N);
            k_vz<<<gG, 256>>>();

            sgemm_bias<<<dim3((NG + BM - 1) / BM, HD2 / BN), 256>>>(
                p_vz, vw1, vb1, p_vt1, NG, HD2, HD, 0);
            k_zero_stats<<<1, 256>>>();
            k_colstats<<<512, 256>>>(p_vt1, NG, HD2);
            k_finalize<<<1, HD2>>>(vbn1g, vbn1b, HD2, 1.0f / NG);

            sgemm_bias<<<dim3((NG + BM - 1) / BM, HD / BN), 256>>>(
                p_vt1, vw2, vb2, p_vt2, NG, HD, HD2, 1);
            k_zero_stats<<<1, 256>>>();
            k_colstats<<<512, 256>>>(p_vt2, NG, HD);
            k_finalize<<<1, HD>>>(vbn2g, vbn2b, HD, 1.0f / NG);
            k_bn_act<<<(NG * HD / 4 + 255) / 256, 256>>>(p_vt2, NG, HD, 1, p_vf, nullptr);
        }
    }

    // readout: mean pool of final feats
    k_zero_pool<<<gG, 256>>>();
    k_pool_scatter<<<gNw, 256>>>(p_feats, batch, 1, N);
    k_readout<<<gG, 256>>>(out + (size_t)N * HD);
    k_copy_vf<<<gG, 256>>>(out + (size_t)N * HD + NG * HD);
}

// round 7
// speedup vs baseline: 1.1205x; 1.1205x over previous
#include <cuda_runtime.h>
#include <cstdint>

#define HD   128
#define HD2  256
#define NMAX 100000
#define NG   512
#define EPS  1e-5f

// ---------------- scratch (static device globals; no allocs) ----------------
__device__ float g_h[(size_t)NMAX * HD];      // gather source h (post-BN feats + vf)
__device__ float g_agg[(size_t)NMAX * HD];    // init h; scatter makes z = h + sum
__device__ float g_t1[(size_t)NMAX * HD2];    // GEMM1 raw output
__device__ float g_t2[(size_t)NMAX * HD];     // GEMM2 raw output (pre outer-BN)
__device__ float g_vf[NG * HD];
__device__ float g_vz[NG * HD];
__device__ float g_vt1[NG * HD2];
__device__ float g_vt2[NG * HD];
__device__ float g_pool[NG * HD];
__device__ float g_cnt[NG];
__device__ float g_sum[HD2];
__device__ float g_sumsq[HD2];
__device__ float g_bnA[HD2];   // inner BN (conv_bn / vmlp bn) scale
__device__ float g_bnC[HD2];   // inner BN shift
__device__ float g_bnA2[HD];   // outer BN scale (per layer, consumed next stage)
__device__ float g_bnC2[HD];

__device__ __forceinline__ void red_add_v4(float* p, float4 v) {
    asm volatile("red.global.add.v4.f32 [%0], {%1, %2, %3, %4};"
                 :: "l"(p), "f"(v.x), "f"(v.y), "f"(v.z), "f"(v.w)
                 : "memory");
}

// cvt.rna.tf32.f32 needs a .b32 destination register
__device__ __forceinline__ float f2tf32(float x) {
    uint32_t y;
    asm("cvt.rna.tf32.f32 %0, %1;" : "=r"(y) : "f"(x));
    return __uint_as_float(y);
}

// ---------------- kernels ----------------

__global__ void k_init_vf(const float* __restrict__ vn_emb) {
    int i = blockIdx.x * blockDim.x + threadIdx.x;
    if (i < NG * HD) g_vf[i] = vn_emb[i & (HD - 1)];
}

// mode 0: h = src (raw, no vf)    [layer 0]
// mode 1: h = relu(src*bnA2+bnC2) + vf[batch]   [layers > 0]
__global__ void k_compute_h(const float* __restrict__ src,
                            const int* __restrict__ batch,
                            int mode, int N) {
    int idx = blockIdx.x * blockDim.x + threadIdx.x;   // float4 index
    int total = N * (HD / 4);
    if (idx >= total) return;
    int row = idx >> 5;            // HD/4 = 32
    int c4  = (idx & 31) << 2;
    float4 v = *(const float4*)&src[(size_t)row * HD + c4];
    if (mode) {
        float4 a = *(const float4*)&g_bnA2[c4];
        float4 c = *(const float4*)&g_bnC2[c4];
        v.x = fmaxf(fmaf(v.x, a.x, c.x), 0.f);
        v.y = fmaxf(fmaf(v.y, a.y, c.y), 0.f);
        v.z = fmaxf(fmaf(v.z, a.z, c.z), 0.f);
        v.w = fmaxf(fmaf(v.w, a.w, c.w), 0.f);
        int g = batch[row];
        float4 u = *(const float4*)&g_vf[g * HD + c4];
        v.x += u.x; v.y += u.y; v.z += u.z; v.w += u.w;
    }
    *(float4*)&g_h[(size_t)row * HD + c4] = v;
    *(float4*)&g_agg[(size_t)row * HD + c4] = v;
}

// one warp per edge: agg[dst] += h[src]  (vector red, 1 instr per lane)
__global__ void k_scatter(const int* __restrict__ ei, int E) {
    int warp = (blockIdx.x * blockDim.x + threadIdx.x) >> 5;
    int lane = threadIdx.x & 31;
    if (warp >= E) return;
    int s = __ldg(&ei[warp]);
    int d = __ldg(&ei[(size_t)E + warp]);
    float4 v = *(const float4*)&g_h[(size_t)s * HD + lane * 4];
    red_add_v4(&g_agg[(size_t)d * HD + lane * 4], v);
}

// ------ 3xTF32 tensor-core GEMM: C = act(A) @ B + bias, fused col stats ----
// Split each operand v = hi + lo (hi = tf32(v), lo = tf32(v - hi)); accumulate
// aH*bH + aL*bH + aH*bL -> fp32-class accuracy on the tensor pipe.
// A [M,K] row-major, B [K,N] row-major. bnOnA: A := relu(A*g_bnA + g_bnC).
// Column sum/sumsq of C (rows < M) accumulated into g_sum/g_sumsq.
#define TBM 128
#define TBN 128
#define TBK 16
#define AS_STRIDE 20   // [m][k] layout, stride 20: conflict-free frag loads
#define BS_STRIDE 136  // [k][n] layout

__global__ __launch_bounds__(256) void mma_gemm(
    const float* __restrict__ A, const float* __restrict__ B,
    const float* __restrict__ bias, float* __restrict__ C,
    int M, int N, int K, int bnOnA)
{
    __shared__ float AsH[TBM][AS_STRIDE];
    __shared__ float AsL[TBM][AS_STRIDE];
    __shared__ float BsH[TBK][BS_STRIDE];
    __shared__ float BsL[TBK][BS_STRIDE];
    __shared__ float sSum[TBN], sSS[TBN];

    int tid = threadIdx.x;
    int lane = tid & 31;
    int warp = tid >> 5;
    int bRow = blockIdx.x * TBM;
    int bCol = blockIdx.y * TBN;
    int warpRow = (warp & 3) * 32;
    int warpCol = (warp >> 2) * 64;

    if (tid < TBN) { sSum[tid] = 0.f; sSS[tid] = 0.f; }

    float acc[2][8][4];
#pragma unroll
    for (int rt = 0; rt < 2; rt++)
#pragma unroll
        for (int ct = 0; ct < 8; ct++)
#pragma unroll
            for (int i = 0; i < 4; i++) acc[rt][ct][i] = 0.f;

    int nk = K / TBK;
    for (int kt = 0; kt < nk; kt++) {
        int k0 = kt * TBK;
        // ---- stage A (with optional BN+ReLU) and B, hi/lo split ----
#pragma unroll
        for (int j = 0; j < 2; j++) {
            int slot = tid + j * 256;
            int ar = slot >> 2;
            int ac = (slot & 3) << 2;
            int grow = bRow + ar;
            float4 v = (grow < M) ? *(const float4*)&A[(size_t)grow * K + k0 + ac]
                                  : make_float4(0.f, 0.f, 0.f, 0.f);
            if (bnOnA) {
                float4 ba = *(const float4*)&g_bnA[k0 + ac];
                float4 bc = *(const float4*)&g_bnC[k0 + ac];
                v.x = fmaxf(fmaf(v.x, ba.x, bc.x), 0.f);
                v.y = fmaxf(fmaf(v.y, ba.y, bc.y), 0.f);
                v.z = fmaxf(fmaf(v.z, ba.z, bc.z), 0.f);
                v.w = fmaxf(fmaf(v.w, ba.w, bc.w), 0.f);
            }
            float4 h, l;
            h.x = f2tf32(v.x); l.x = f2tf32(v.x - h.x);
            h.y = f2tf32(v.y); l.y = f2tf32(v.y - h.y);
            h.z = f2tf32(v.z); l.z = f2tf32(v.z - h.z);
            h.w = f2tf32(v.w); l.w = f2tf32(v.w - h.w);
            *(float4*)&AsH[ar][ac] = h;
            *(float4*)&AsL[ar][ac] = l;
        }
#pragma unroll
        for (int j = 0; j < 2; j++) {
            int slot = tid + j * 256;
            int br = slot >> 5;
            int bc = (slot & 31) << 2;
            float4 v = *(const float4*)&B[(size_t)(k0 + br) * N + bCol + bc];
            float4 h, l;
            h.x = f2tf32(v.x); l.x = f2tf32(v.x - h.x);
            h.y = f2tf32(v.y); l.y = f2tf32(v.y - h.y);
            h.z = f2tf32(v.z); l.z = f2tf32(v.z - h.z);
            h.w = f2tf32(v.w); l.w = f2tf32(v.w - h.w);
            *(float4*)&BsH[br][bc] = h;
            *(float4*)&BsL[br][bc] = l;
        }
        __syncthreads();

#pragma unroll
        for (int ks = 0; ks < 2; ks++) {
            int kc = ks * 8 + (lane & 3);
            uint32_t aH[2][4], aL[2][4];
#pragma unroll
            for (int rt = 0; rt < 2; rt++) {
                int r = warpRow + rt * 16 + (lane >> 2);
                aH[rt][0] = __float_as_uint(AsH[r][kc]);
                aH[rt][1] = __float_as_uint(AsH[r + 8][kc]);
                aH[rt][2] = __float_as_uint(AsH[r][kc + 4]);
                aH[rt][3] = __float_as_uint(AsH[r + 8][kc + 4]);
                aL[rt][0] = __float_as_uint(AsL[r][kc]);
                aL[rt][1] = __float_as_uint(AsL[r + 8][kc]);
                aL[rt][2] = __float_as_uint(AsL[r][kc + 4]);
                aL[rt][3] = __float_as_uint(AsL[r + 8][kc + 4]);
            }
#pragma unroll
            for (int ct = 0; ct < 8; ct++) {
                int c = warpCol + ct * 8 + (lane >> 2);
                uint32_t bH0 = __float_as_uint(BsH[kc][c]);
                uint32_t bH1 = __float_as_uint(BsH[kc + 4][c]);
                uint32_t bL0 = __float_as_uint(BsL[kc][c]);
                uint32_t bL1 = __float_as_uint(BsL[kc + 4][c]);
#pragma unroll
                for (int rt = 0; rt < 2; rt++) {
#define MMA(A0,A1,A2,A3,B0,B1)                                                \
                    asm volatile(                                             \
                        "mma.sync.aligned.m16n8k8.row.col.f32.tf32.tf32.f32 " \
                        "{%0,%1,%2,%3}, {%4,%5,%6,%7}, {%8,%9}, {%0,%1,%2,%3};" \
                        : "+f"(acc[rt][ct][0]), "+f"(acc[rt][ct][1]),         \
                          "+f"(acc[rt][ct][2]), "+f"(acc[rt][ct][3])          \
                        : "r"(A0), "r"(A1), "r"(A2), "r"(A3),                 \
                          "r"(B0), "r"(B1))
                    MMA(aL[rt][0], aL[rt][1], aL[rt][2], aL[rt][3], bH0, bH1);
                    MMA(aH[rt][0], aH[rt][1], aH[rt][2], aH[rt][3], bL0, bL1);
                    MMA(aH[rt][0], aH[rt][1], aH[rt][2], aH[rt][3], bH0, bH1);
#undef MMA
                }
            }
        }
        __syncthreads();
    }

    // ---- epilogue: bias, store, fused column stats ----
#pragma unroll
    for (int ct = 0; ct < 8; ct++) {
        int j = warpCol + ct * 8 + 2 * (lane & 3);
        float b0v = bias[bCol + j];
        float b1v = bias[bCol + j + 1];
#pragma unroll
        for (int rt = 0; rt < 2; rt++) {
            acc[rt][ct][0] += b0v; acc[rt][ct][1] += b1v;
            acc[rt][ct][2] += b0v; acc[rt][ct][3] += b1v;
        }
    }
#pragma unroll
    for (int rt = 0; rt < 2; rt++) {
        int r0 = bRow + warpRow + rt * 16 + (lane >> 2);
        int r1 = r0 + 8;
#pragma unroll
        for (int ct = 0; ct < 8; ct++) {
            int j = bCol + warpCol + ct * 8 + 2 * (lane & 3);
            if (r0 < M) *(float2*)&C[(size_t)r0 * N + j] =
                make_float2(acc[rt][ct][0], acc[rt][ct][1]);
            if (r1 < M) *(float2*)&C[(size_t)r1 * N + j] =
                make_float2(acc[rt][ct][2], acc[rt][ct][3]);
        }
    }
    // column stats over this block's rows
#pragma unroll
    for (int ct = 0; ct < 8; ct++) {
        float s0 = 0.f, q0 = 0.f, s1 = 0.f, q1 = 0.f;
#pragma unroll
        for (int rt = 0; rt < 2; rt++) {
            int r0 = bRow + warpRow + rt * 16 + (lane >> 2);
            int r1 = r0 + 8;
            if (r0 < M) {
                float v = acc[rt][ct][0]; s0 += v; q0 += v * v;
                v = acc[rt][ct][1]; s1 += v; q1 += v * v;
            }
            if (r1 < M) {
                float v = acc[rt][ct][2]; s0 += v; q0 += v * v;
                v = acc[rt][ct][3]; s1 += v; q1 += v * v;
            }
        }
#pragma unroll
        for (int m = 4; m < 32; m <<= 1) {
            s0 += __shfl_xor_sync(0xFFFFFFFF, s0, m);
            q0 += __shfl_xor_sync(0xFFFFFFFF, q0, m);
            s1 += __shfl_xor_sync(0xFFFFFFFF, s1, m);
            q1 += __shfl_xor_sync(0xFFFFFFFF, q1, m);
        }
        if ((lane >> 2) == 0) {
            int j = warpCol + ct * 8 + 2 * (lane & 3);
            atomicAdd(&sSum[j], s0); atomicAdd(&sSS[j], q0);
            atomicAdd(&sSum[j + 1], s1); atomicAdd(&sSS[j + 1], q1);
        }
    }
    __syncthreads();
    if (tid < TBN) {
        atomicAdd(&g_sum[bCol + tid], sSum[tid]);
        atomicAdd(&g_sumsq[bCol + tid], sSS[tid]);
    }
}

__global__ void k_zero_stats() {
    int t = threadIdx.x;
    g_sum[t] = 0.f;
    g_sumsq[t] = 0.f;
}

__global__ void k_finalize(const float* __restrict__ gamma,
                           const float* __restrict__ beta,
                           int C, float invM,
                           float* __restrict__ outA, float* __restrict__ outC) {
    int t = threadIdx.x;
    if (t >= C) return;
    float mean = g_sum[t] * invM;
    float var = g_sumsq[t] * invM - mean * mean;
    float r = rsqrtf(var + EPS);
    float a = gamma[t] * r;
    outA[t] = a;
    outC[t] = beta[t] - mean * a;
}

// y = act(x*a + c) -> dst1
__global__ void k_bn_act(const float* __restrict__ X, int M, int C, int doRelu,
                         const float* __restrict__ bnA, const float* __restrict__ bnC,
                         float* __restrict__ dst1) {
    int idx = blockIdx.x * blockDim.x + threadIdx.x;   // float4 index
    int total = M * C / 4;
    if (idx >= total) return;
    size_t off = (size_t)idx * 4;
    int col = (int)(off % C);
    float4 v = *(const float4*)&X[off];
    float4 a = *(const float4*)&bnA[col];
    float4 c = *(const float4*)&bnC[col];
    float4 y;
    y.x = fmaf(v.x, a.x, c.x);
    y.y = fmaf(v.y, a.y, c.y);
    y.z = fmaf(v.z, a.z, c.z);
    y.w = fmaf(v.w, a.w, c.w);
    if (doRelu) {
        y.x = fmaxf(y.x, 0.f); y.y = fmaxf(y.y, 0.f);
        y.z = fmaxf(y.z, 0.f); y.w = fmaxf(y.w, 0.f);
    }
    *(float4*)&dst1[off] = y;
}

__global__ void k_zero_pool() {
    int i = blockIdx.x * blockDim.x + threadIdx.x;
    if (i < NG * HD) g_pool[i] = 0.f;
    if (i < NG) g_cnt[i] = 0.f;
}

// one warp per node: pool[batch[n]] += act(bn2(X[n])); counts optional
__global__ void k_pool_scatter(const float* __restrict__ X,
                               const int* __restrict__ batch,
                               int doRelu, int addCounts, int N) {
    int warp = (blockIdx.x * blockDim.x + threadIdx.x) >> 5;
    int lane = threadIdx.x & 31;
    if (warp >= N) return;
    int g = batch[warp];
    int c4 = lane * 4;
    float4 v = *(const float4*)&X[(size_t)warp * HD + c4];
    float4 a = *(const float4*)&g_bnA2[c4];
    float4 c = *(const float4*)&g_bnC2[c4];
    float4 y;
    y.x = fmaf(v.x, a.x, c.x);
    y.y = fmaf(v.y, a.y, c.y);
    y.z = fmaf(v.z, a.z, c.z);
    y.w = fmaf(v.w, a.w, c.w);
    if (doRelu) {
        y.x = fmaxf(y.x, 0.f); y.y = fmaxf(y.y, 0.f);
        y.z = fmaxf(y.z, 0.f); y.w = fmaxf(y.w, 0.f);
    }
    red_add_v4(&g_pool[g * HD + c4], y);
    if (addCounts && lane == 0) atomicAdd(&g_cnt[g], 1.f);
}

__global__ void k_vz() {
    int i = blockIdx.x * blockDim.x + threadIdx.x;
    if (i < NG * HD) g_vz[i] = g_pool[i] + g_vf[i];
}

__global__ void k_readout(float* __restrict__ out) {
    int i = blockIdx.x * blockDim.x + threadIdx.x;
    if (i < NG * HD) out[i] = g_pool[i] / fmaxf(g_cnt[i >> 7], 1.f);
}

__global__ void k_copy_vf(float* __restrict__ out) {
    int i = blockIdx.x * blockDim.x + threadIdx.x;
    if (i < NG * HD) out[i] = g_vf[i];
}

// ---------------- host ----------------
extern "C" void kernel_launch(void* const* d_in, const int* in_sizes, int n_in,
                              void* d_out, int out_size) {
    const float* x = (const float*)d_in[0];
    const int* ei = (const int*)d_in[1];      // int32 (JAX x64 disabled)
    const int* batch = (const int*)d_in[2];   // int32
    int base = 3;
    if (n_in > 3 && in_sizes[3] <= 2) base = 4;  // num_graphs scalar present
    const float* conv_w1 = (const float*)d_in[base + 0];
    const float* conv_b1 = (const float*)d_in[base + 1];
    const float* conv_bn_g = (const float*)d_in[base + 2];
    const float* conv_bn_b = (const float*)d_in[base + 3];
    const float* conv_w2 = (const float*)d_in[base + 4];
    const float* conv_b2 = (const float*)d_in[base + 5];
    const float* bn_g = (const float*)d_in[base + 6];
    const float* bn_b = (const float*)d_in[base + 7];
    const float* vn_emb = (const float*)d_in[base + 8];
    const float* vw1 = (const float*)d_in[base + 9];
    const float* vb1 = (const float*)d_in[base + 10];
    const float* vbn1g = (const float*)d_in[base + 11];
    const float* vbn1b = (const float*)d_in[base + 12];
    const float* vw2 = (const float*)d_in[base + 13];
    const float* vb2 = (const float*)d_in[base + 14];
    const float* vbn2g = (const float*)d_in[base + 15];
    const float* vbn2b = (const float*)d_in[base + 16];

    int N = in_sizes[0] / HD;
    int E = in_sizes[1] / 2;
    float* out = (float*)d_out;

    float *p_agg, *p_t1, *p_t2, *p_vz, *p_vt1, *p_vt2, *p_vf;
    float *p_bnA, *p_bnC, *p_bnA2, *p_bnC2;
    cudaGetSymbolAddress((void**)&p_agg, g_agg);
    cudaGetSymbolAddress((void**)&p_t1, g_t1);
    cudaGetSymbolAddress((void**)&p_t2, g_t2);
    cudaGetSymbolAddress((void**)&p_vz, g_vz);
    cudaGetSymbolAddress((void**)&p_vt1, g_vt1);
    cudaGetSymbolAddress((void**)&p_vt2, g_vt2);
    cudaGetSymbolAddress((void**)&p_vf, g_vf);
    cudaGetSymbolAddress((void**)&p_bnA, g_bnA);
    cudaGetSymbolAddress((void**)&p_bnC, g_bnC);
    cudaGetSymbolAddress((void**)&p_bnA2, g_bnA2);
    cudaGetSymbolAddress((void**)&p_bnC2, g_bnC2);

    int gN4 = (N * (HD / 4) + 255) / 256;        // elementwise over [N,HD]
    int gE = (E * 32 + 255) / 256;               // warp per edge
    int gNw = (N * 32 + 255) / 256;              // warp per node
    int gG = (NG * HD + 255) / 256;
    int gM = (N + TBM - 1) / TBM;
    int gV = (NG + TBM - 1) / TBM;

    k_init_vf<<<gG, 256>>>(vn_emb);

    for (int i = 0; i < 3; i++) {
        const float* src = (i == 0) ? x : p_t2;
        k_compute_h<<<gN4, 256>>>(src, batch, i > 0 ? 1 : 0, N);
        k_scatter<<<gE, 256>>>(ei, E);     // g_agg becomes z = h + sum

        // GEMM1 (z @ w1 + b1) -> t1 raw, stats fused
        k_zero_stats<<<1, 256>>>();
        mma_gemm<<<dim3(gM, HD2 / TBN), 256>>>(
            p_agg, conv_w1 + (size_t)i * HD * HD2, conv_b1 + i * HD2,
            p_t1, N, HD2, HD, 0);
        k_finalize<<<1, HD2>>>(conv_bn_g + i * HD2, conv_bn_b + i * HD2,
                               HD2, 1.0f / N, p_bnA, p_bnC);

        // GEMM2 with inner BN+ReLU fused on A -> t2 raw, stats fused
        k_zero_stats<<<1, 256>>>();
        mma_gemm<<<dim3(gM, HD / TBN), 256>>>(
            p_t1, conv_w2 + (size_t)i * HD2 * HD, conv_b2 + i * HD,
            p_t2, N, HD, HD2, 1);
        k_finalize<<<1, HD>>>(bn_g + i * HD, bn_b + i * HD,
                              HD, 1.0f / N, p_bnA2, p_bnC2);

        if (i == 2) {
            // feats output: bn2(t2), no relu
            k_bn_act<<<gN4, 256>>>(p_t2, N, HD, 0, p_bnA2, p_bnC2, out);
        }

        // virtual node update (only i == 1 for L=3)
        if (i == 1) {
            k_zero_pool<<<gG, 256>>>();
            k_pool_scatter<<<gNw, 256>>>(p_t2, batch, 1, 0, N);  // bn2+relu
            k_vz<<<gG, 256>>>();

            k_zero_stats<<<1, 256>>>();
            mma_gemm<<<dim3(gV, HD2 / TBN), 256>>>(p_vz, vw1, vb1, p_vt1,
                                                   NG, HD2, HD, 0);
            k_finalize<<<1, HD2>>>(vbn1g, vbn1b, HD2, 1.0f / NG, p_bnA, p_bnC);

            k_zero_stats<<<1, 256>>>();
            mma_gemm<<<dim3(gV, HD / TBN), 256>>>(p_vt1, vw2, vb2, p_vt2,
                                                  NG, HD, HD2, 1);
            k_finalize<<<1, HD>>>(vbn2g, vbn2b, HD, 1.0f / NG, p_bnA, p_bnC);
            k_bn_act<<<(NG * HD / 4 + 255) / 256, 256>>>(
                p_vt2, NG, HD, 1, p_bnA, p_bnC, p_vf);
        }
    }

    // readout: mean pool of bn2(t2) (layer-3 feats, no relu)
    k_zero_pool<<<gG, 256>>>();
    k_pool_scatter<<<gNw, 256>>>(p_t2, batch, 0, 1, N);
    k_readout<<<gG, 256>>>(out + (size_t)N * HD);
    k_copy_vf<<<gG, 256>>>(out + (size_t)N * HD + NG * HD);
}

// round 9
// speedup vs baseline: 1.4023x; 1.2515x over previous
#include <cuda_runtime.h>
#include <cstdint>

#define HD   128
#define HD2  256
#define NMAX 100000
#define EMAX 1600000
#define NG   512
#define EPS  1e-5f

// ---------------- scratch (static device globals; no allocs) ----------------
__device__ float g_h[(size_t)NMAX * HD];      // gather source h (post-BN feats + vf)
__device__ float g_agg[(size_t)NMAX * HD];    // z = h + sum_in h[src]
__device__ float g_t1[(size_t)NMAX * HD2];    // GEMM1 raw output
__device__ float g_t2[(size_t)NMAX * HD];     // GEMM2 raw output (pre outer-BN)
__device__ float g_vf[NG * HD];
__device__ float g_vz[NG * HD];
__device__ float g_vt1[NG * HD2];
__device__ float g_vt2[NG * HD];
__device__ float g_pool[NG * HD];
__device__ float g_cnt[NG];
__device__ float g_sum[HD2];     // zero-init at load; k_finalize re-zeros after read
__device__ float g_sumsq[HD2];
__device__ float g_bnA[HD2];
__device__ float g_bnC[HD2];
__device__ float g_bnA2[HD];
__device__ float g_bnC2[HD];
// CSR build (graph static across layers; rebuilt identically every launch)
__device__ int g_deg[NMAX];
__device__ int g_rowptr[NMAX];
__device__ int g_pos[NMAX];
__device__ int g_bsum[128];
__device__ int g_boff[128];
__device__ int g_eidx[EMAX];

__device__ __forceinline__ void red_add_v4(float* p, float4 v) {
    asm volatile("red.global.add.v4.f32 [%0], {%1, %2, %3, %4};"
                 :: "l"(p), "f"(v.x), "f"(v.y), "f"(v.z), "f"(v.w)
                 : "memory");
}

__device__ __forceinline__ float f2tf32(float x) {
    uint32_t y;
    asm("cvt.rna.tf32.f32 %0, %1;" : "=r"(y) : "f"(x));
    return __uint_as_float(y);
}

// ---------------- CSR build ----------------

__global__ void k_zero_deg(int N) {
    int i = blockIdx.x * blockDim.x + threadIdx.x;
    if (i < N) g_deg[i] = 0;
}

__global__ void k_hist(const int* __restrict__ ei, int E) {
    int e = blockIdx.x * blockDim.x + threadIdx.x;
    if (e < E) atomicAdd(&g_deg[ei[(size_t)E + e]], 1);
}

// block scan: 1024 deg values per block (256 thr x 4); exclusive into rowptr
__global__ void k_scan1(int N) {
    __shared__ int ts[256];
    int b = blockIdx.x, t = threadIdx.x;
    int base = b * 1024 + t * 4;
    int v0 = (base + 0 < N) ? g_deg[base + 0] : 0;
    int v1 = (base + 1 < N) ? g_deg[base + 1] : 0;
    int v2 = (base + 2 < N) ? g_deg[base + 2] : 0;
    int v3 = (base + 3 < N) ? g_deg[base + 3] : 0;
    int s = v0 + v1 + v2 + v3;
    ts[t] = s;
    __syncthreads();
    for (int off = 1; off < 256; off <<= 1) {
        int x = (t >= off) ? ts[t - off] : 0;
        __syncthreads();
        ts[t] += x;
        __syncthreads();
    }
    int excl = ts[t] - s;
    if (base + 0 < N) g_rowptr[base + 0] = excl; excl += v0;
    if (base + 1 < N) g_rowptr[base + 1] = excl; excl += v1;
    if (base + 2 < N) g_rowptr[base + 2] = excl; excl += v2;
    if (base + 3 < N) g_rowptr[base + 3] = excl;
    if (t == 255) g_bsum[b] = ts[255];
}

__global__ void k_scan2(int NB) {
    __shared__ int bs[128];
    int t = threadIdx.x;
    int v = (t < NB) ? g_bsum[t] : 0;
    bs[t] = v;
    __syncthreads();
    for (int off = 1; off < 128; off <<= 1) {
        int x = (t >= off) ? bs[t - off] : 0;
        __syncthreads();
        bs[t] += x;
        __syncthreads();
    }
    if (t < NB) g_boff[t] = bs[t] - v;   // exclusive
}

__global__ void k_scan3(int N) {
    int i = blockIdx.x * blockDim.x + threadIdx.x;
    if (i < N) {
        int r = g_rowptr[i] + g_boff[i >> 10];
        g_rowptr[i] = r;
        g_pos[i] = r;
    }
}

__global__ void k_fill(const int* __restrict__ ei, int E) {
    int e = blockIdx.x * blockDim.x + threadIdx.x;
    if (e >= E) return;
    int s = ei[e];
    int d = ei[(size_t)E + e];
    int p = atomicAdd(&g_pos[d], 1);
    g_eidx[p] = s;
}

// ---------------- per-layer kernels ----------------

__global__ void k_init_vf(const float* __restrict__ vn_emb) {
    int i = blockIdx.x * blockDim.x + threadIdx.x;
    if (i < NG * HD) g_vf[i] = vn_emb[i & (HD - 1)];
}

// mode 0: h = src (raw)           [layer 0]
// mode 1: h = relu(src*bnA2+bnC2) + vf[batch]   [layers > 0]
__global__ void k_compute_h(const float* __restrict__ src,
                            const int* __restrict__ batch,
                            int mode, int N) {
    int idx = blockIdx.x * blockDim.x + threadIdx.x;   // float4 index
    int total = N * (HD / 4);
    if (idx >= total) return;
    int row = idx >> 5;
    int c4  = (idx & 31) << 2;
    float4 v = *(const float4*)&src[(size_t)row * HD + c4];
    if (mode) {
        float4 a = *(const float4*)&g_bnA2[c4];
        float4 c = *(const float4*)&g_bnC2[c4];
        v.x = fmaxf(fmaf(v.x, a.x, c.x), 0.f);
        v.y = fmaxf(fmaf(v.y, a.y, c.y), 0.f);
        v.z = fmaxf(fmaf(v.z, a.z, c.z), 0.f);
        v.w = fmaxf(fmaf(v.w, a.w, c.w), 0.f);
        int g = batch[row];
        float4 u = *(const float4*)&g_vf[g * HD + c4];
        v.x += u.x; v.y += u.y; v.z += u.z; v.w += u.w;
    }
    *(float4*)&g_h[(size_t)row * HD + c4] = v;
}

// warp per node: z[n] = h[n] + sum_{e: dst=n} h[src_e]   (pure gather via CSR)
__global__ void k_gather(int N) {
    int warp = (blockIdx.x * blockDim.x + threadIdx.x) >> 5;
    int lane = threadIdx.x & 31;
    if (warp >= N) return;
    int c4 = lane * 4;
    float4 acc = *(const float4*)&g_h[(size_t)warp * HD + c4];
    int j = g_rowptr[warp];
    int end = j + g_deg[warp];
    // unroll 4 for MLP
    for (; j + 4 <= end; j += 4) {
        int s0 = g_eidx[j], s1 = g_eidx[j + 1];
        int s2 = g_eidx[j + 2], s3 = g_eidx[j + 3];
        float4 a = *(const float4*)&g_h[(size_t)s0 * HD + c4];
        float4 b = *(const float4*)&g_h[(size_t)s1 * HD + c4];
        float4 c = *(const float4*)&g_h[(size_t)s2 * HD + c4];
        float4 d = *(const float4*)&g_h[(size_t)s3 * HD + c4];
        acc.x += a.x + b.x + c.x + d.x;
        acc.y += a.y + b.y + c.y + d.y;
        acc.z += a.z + b.z + c.z + d.z;
        acc.w += a.w + b.w + c.w + d.w;
    }
    for (; j < end; j++) {
        int s = g_eidx[j];
        float4 a = *(const float4*)&g_h[(size_t)s * HD + c4];
        acc.x += a.x; acc.y += a.y; acc.z += a.z; acc.w += a.w;
    }
    *(float4*)&g_agg[(size_t)warp * HD + c4] = acc;
}

// ------ 3xTF32 tensor-core GEMM: C = act(A) @ B + bias, fused col stats ----
#define TBM 128
#define TBN 128
#define TBK 16
#define AS_STRIDE 20
#define BS_STRIDE 136

__global__ __launch_bounds__(256) void mma_gemm(
    const float* __restrict__ A, const float* __restrict__ B,
    const float* __restrict__ bias, float* __restrict__ C,
    int M, int N, int K, int bnOnA)
{
    __shared__ float AsH[TBM][AS_STRIDE];
    __shared__ float AsL[TBM][AS_STRIDE];
    __shared__ float BsH[TBK][BS_STRIDE];
    __shared__ float BsL[TBK][BS_STRIDE];
    __shared__ float sSum[TBN], sSS[TBN];

    int tid = threadIdx.x;
    int lane = tid & 31;
    int warp = tid >> 5;
    int bRow = blockIdx.x * TBM;
    int bCol = blockIdx.y * TBN;
    int warpRow = (warp & 3) * 32;
    int warpCol = (warp >> 2) * 64;

    if (tid < TBN) { sSum[tid] = 0.f; sSS[tid] = 0.f; }

    float acc[2][8][4];
#pragma unroll
    for (int rt = 0; rt < 2; rt++)
#pragma unroll
        for (int ct = 0; ct < 8; ct++)
#pragma unroll
            for (int i = 0; i < 4; i++) acc[rt][ct][i] = 0.f;

    int nk = K / TBK;
    for (int kt = 0; kt < nk; kt++) {
        int k0 = kt * TBK;
#pragma unroll
        for (int j = 0; j < 2; j++) {
            int slot = tid + j * 256;
            int ar = slot >> 2;
            int ac = (slot & 3) << 2;
            int grow = bRow + ar;
            float4 v = (grow < M) ? *(const float4*)&A[(size_t)grow * K + k0 + ac]
                                  : make_float4(0.f, 0.f, 0.f, 0.f);
            if (bnOnA) {
                float4 ba = *(const float4*)&g_bnA[k0 + ac];
                float4 bc = *(const float4*)&g_bnC[k0 + ac];
                v.x = fmaxf(fmaf(v.x, ba.x, bc.x), 0.f);
                v.y = fmaxf(fmaf(v.y, ba.y, bc.y), 0.f);
                v.z = fmaxf(fmaf(v.z, ba.z, bc.z), 0.f);
                v.w = fmaxf(fmaf(v.w, ba.w, bc.w), 0.f);
            }
            float4 h, l;
            h.x = f2tf32(v.x); l.x = f2tf32(v.x - h.x);
            h.y = f2tf32(v.y); l.y = f2tf32(v.y - h.y);
            h.z = f2tf32(v.z); l.z = f2tf32(v.z - h.z);
            h.w = f2tf32(v.w); l.w = f2tf32(v.w - h.w);
            *(float4*)&AsH[ar][ac] = h;
            *(float4*)&AsL[ar][ac] = l;
        }
#pragma unroll
        for (int j = 0; j < 2; j++) {
            int slot = tid + j * 256;
            int br = slot >> 5;
            int bc = (slot & 31) << 2;
            float4 v = *(const float4*)&B[(size_t)(k0 + br) * N + bCol + bc];
            float4 h, l;
            h.x = f2tf32(v.x); l.x = f2tf32(v.x - h.x);
            h.y = f2tf32(v.y); l.y = f2tf32(v.y - h.y);
            h.z = f2tf32(v.z); l.z = f2tf32(v.z - h.z);
            h.w = f2tf32(v.w); l.w = f2tf32(v.w - h.w);
            *(float4*)&BsH[br][bc] = h;
            *(float4*)&BsL[br][bc] = l;
        }
        __syncthreads();

#pragma unroll
        for (int ks = 0; ks < 2; ks++) {
            int kc = ks * 8 + (lane & 3);
            uint32_t aH[2][4], aL[2][4];
#pragma unroll
            for (int rt = 0; rt < 2; rt++) {
                int r = warpRow + rt * 16 + (lane >> 2);
                aH[rt][0] = __float_as_uint(AsH[r][kc]);
                aH[rt][1] = __float_as_uint(AsH[r + 8][kc]);
                aH[rt][2] = __float_as_uint(AsH[r][kc + 4]);
                aH[rt][3] = __float_as_uint(AsH[r + 8][kc + 4]);
                aL[rt][0] = __float_as_uint(AsL[r][kc]);
                aL[rt][1] = __float_as_uint(AsL[r + 8][kc]);
                aL[rt][2] = __float_as_uint(AsL[r][kc + 4]);
                aL[rt][3] = __float_as_uint(AsL[r + 8][kc + 4]);
            }
#pragma unroll
            for (int ct = 0; ct < 8; ct++) {
                int c = warpCol + ct * 8 + (lane >> 2);
                uint32_t bH0 = __float_as_uint(BsH[kc][c]);
                uint32_t bH1 = __float_as_uint(BsH[kc + 4][c]);
                uint32_t bL0 = __float_as_uint(BsL[kc][c]);
                uint32_t bL1 = __float_as_uint(BsL[kc + 4][c]);
#pragma unroll
                for (int rt = 0; rt < 2; rt++) {
#define MMA(A0,A1,A2,A3,B0,B1)                                                \
                    asm volatile(                                             \
                        "mma.sync.aligned.m16n8k8.row.col.f32.tf32.tf32.f32 " \
                        "{%0,%1,%2,%3}, {%4,%5,%6,%7}, {%8,%9}, {%0,%1,%2,%3};" \
                        : "+f"(acc[rt][ct][0]), "+f"(acc[rt][ct][1]),         \
                          "+f"(acc[rt][ct][2]), "+f"(acc[rt][ct][3])          \
                        : "r"(A0), "r"(A1), "r"(A2), "r"(A3),                 \
                          "r"(B0), "r"(B1))
                    MMA(aL[rt][0], aL[rt][1], aL[rt][2], aL[rt][3], bH0, bH1);
                    MMA(aH[rt][0], aH[rt][1], aH[rt][2], aH[rt][3], bL0, bL1);
                    MMA(aH[rt][0], aH[rt][1], aH[rt][2], aH[rt][3], bH0, bH1);
#undef MMA
                }
            }
        }
        __syncthreads();
    }

    // ---- epilogue: bias, store, fused column stats ----
#pragma unroll
    for (int ct = 0; ct < 8; ct++) {
        int j = warpCol + ct * 8 + 2 * (lane & 3);
        float b0v = bias[bCol + j];
        float b1v = bias[bCol + j + 1];
#pragma unroll
        for (int rt = 0; rt < 2; rt++) {
            acc[rt][ct][0] += b0v; acc[rt][ct][1] += b1v;
            acc[rt][ct][2] += b0v; acc[rt][ct][3] += b1v;
        }
    }
#pragma unroll
    for (int rt = 0; rt < 2; rt++) {
        int r0 = bRow + warpRow + rt * 16 + (lane >> 2);
        int r1 = r0 + 8;
#pragma unroll
        for (int ct = 0; ct < 8; ct++) {
            int j = bCol + warpCol + ct * 8 + 2 * (lane & 3);
            if (r0 < M) *(float2*)&C[(size_t)r0 * N + j] =
                make_float2(acc[rt][ct][0], acc[rt][ct][1]);
            if (r1 < M) *(float2*)&C[(size_t)r1 * N + j] =
                make_float2(acc[rt][ct][2], acc[rt][ct][3]);
        }
    }
#pragma unroll
    for (int ct = 0; ct < 8; ct++) {
        float s0 = 0.f, q0 = 0.f, s1 = 0.f, q1 = 0.f;
#pragma unroll
        for (int rt = 0; rt < 2; rt++) {
            int r0 = bRow + warpRow + rt * 16 + (lane >> 2);
            int r1 = r0 + 8;
            if (r0 < M) {
                float v = acc[rt][ct][0]; s0 += v; q0 += v * v;
                v = acc[rt][ct][1]; s1 += v; q1 += v * v;
            }
            if (r1 < M) {
                float v = acc[rt][ct][2]; s0 += v; q0 += v * v;
                v = acc[rt][ct][3]; s1 += v; q1 += v * v;
            }
        }
#pragma unroll
        for (int m = 4; m < 32; m <<= 1) {
            s0 += __shfl_xor_sync(0xFFFFFFFF, s0, m);
            q0 += __shfl_xor_sync(0xFFFFFFFF, q0, m);
            s1 += __shfl_xor_sync(0xFFFFFFFF, s1, m);
            q1 += __shfl_xor_sync(0xFFFFFFFF, q1, m);
        }
        if ((lane >> 2) == 0) {
            int j = warpCol + ct * 8 + 2 * (lane & 3);
            atomicAdd(&sSum[j], s0); atomicAdd(&sSS[j], q0);
            atomicAdd(&sSum[j + 1], s1); atomicAdd(&sSS[j + 1], q1);
        }
    }
    __syncthreads();
    if (tid < TBN) {
        atomicAdd(&g_sum[bCol + tid], sSum[tid]);
        atomicAdd(&g_sumsq[bCol + tid], sSS[tid]);
    }
}

// reads stats, computes scale/shift, re-zeros stats for the next GEMM
__global__ void k_finalize(const float* __restrict__ gamma,
                           const float* __restrict__ beta,
                           int C, float invM,
                           float* __restrict__ outA, float* __restrict__ outC) {
    int t = threadIdx.x;
    if (t >= C) return;
    float mean = g_sum[t] * invM;
    float var = g_sumsq[t] * invM - mean * mean;
    float r = rsqrtf(var + EPS);
    float a = gamma[t] * r;
    outA[t] = a;
    outC[t] = beta[t] - mean * a;
    g_sum[t] = 0.f;
    g_sumsq[t] = 0.f;
}

__global__ void k_bn_act(const float* __restrict__ X, int M, int C, int doRelu,
                         const float* __restrict__ bnA, const float* __restrict__ bnC,
                         float* __restrict__ dst1) {
    int idx = blockIdx.x * blockDim.x + threadIdx.x;
    int total = M * C / 4;
    if (idx >= total) return;
    size_t off = (size_t)idx * 4;
    int col = (int)(off % C);
    float4 v = *(const float4*)&X[off];
    float4 a = *(const float4*)&bnA[col];
    float4 c = *(const float4*)&bnC[col];
    float4 y;
    y.x = fmaf(v.x, a.x, c.x);
    y.y = fmaf(v.y, a.y, c.y);
    y.z = fmaf(v.z, a.z, c.z);
    y.w = fmaf(v.w, a.w, c.w);
    if (doRelu) {
        y.x = fmaxf(y.x, 0.f); y.y = fmaxf(y.y, 0.f);
        y.z = fmaxf(y.z, 0.f); y.w = fmaxf(y.w, 0.f);
    }
    *(float4*)&dst1[off] = y;
}

__global__ void k_zero_pool() {
    int i = blockIdx.x * blockDim.x + threadIdx.x;
    if (i < NG * HD) g_pool[i] = 0.f;
    if (i < NG) g_cnt[i] = 0.f;
}

__global__ void k_pool_scatter(const float* __restrict__ X,
                               const int* __restrict__ batch,
                               int doRelu, int addCounts, int N) {
    int warp = (blockIdx.x * blockDim.x + threadIdx.x) >> 5;
    int lane = threadIdx.x & 31;
    if (warp >= N) return;
    int g = batch[warp];
    int c4 = lane * 4;
    float4 v = *(const float4*)&X[(size_t)warp * HD + c4];
    float4 a = *(const float4*)&g_bnA2[c4];
    float4 c = *(const float4*)&g_bnC2[c4];
    float4 y;
    y.x = fmaf(v.x, a.x, c.x);
    y.y = fmaf(v.y, a.y, c.y);
    y.z = fmaf(v.z, a.z, c.z);
    y.w = fmaf(v.w, a.w, c.w);
    if (doRelu) {
        y.x = fmaxf(y.x, 0.f); y.y = fmaxf(y.y, 0.f);
        y.z = fmaxf(y.z, 0.f); y.w = fmaxf(y.w, 0.f);
    }
    red_add_v4(&g_pool[g * HD + c4], y);
    if (addCounts && lane == 0) atomicAdd(&g_cnt[g], 1.f);
}

__global__ void k_vz() {
    int i = blockIdx.x * blockDim.x + threadIdx.x;
    if (i < NG * HD) g_vz[i] = g_pool[i] + g_vf[i];
}

__global__ void k_readout(float* __restrict__ out) {
    int i = blockIdx.x * blockDim.x + threadIdx.x;
    if (i < NG * HD) out[i] = g_pool[i] / fmaxf(g_cnt[i >> 7], 1.f);
}

__global__ void k_copy_vf(float* __restrict__ out) {
    int i = blockIdx.x * blockDim.x + threadIdx.x;
    if (i < NG * HD) out[i] = g_vf[i];
}

// ---------------- host ----------------
extern "C" void kernel_launch(void* const* d_in, const int* in_sizes, int n_in,
                              void* d_out, int out_size) {
    const float* x = (const float*)d_in[0];
    const int* ei = (const int*)d_in[1];
    const int* batch = (const int*)d_in[2];
    int base = 3;
    if (n_in > 3 && in_sizes[3] <= 2) base = 4;
    const float* conv_w1 = (const float*)d_in[base + 0];
    const float* conv_b1 = (const float*)d_in[base + 1];
    const float* conv_bn_g = (const float*)d_in[base + 2];
    const float* conv_bn_b = (const float*)d_in[base + 3];
    const float* conv_w2 = (const float*)d_in[base + 4];
    const float* conv_b2 = (const float*)d_in[base + 5];
    const float* bn_g = (const float*)d_in[base + 6];
    const float* bn_b = (const float*)d_in[base + 7];
    const float* vn_emb = (const float*)d_in[base + 8];
    const float* vw1 = (const float*)d_in[base + 9];
    const float* vb1 = (const float*)d_in[base + 10];
    const float* vbn1g = (const float*)d_in[base + 11];
    const float* vbn1b = (const float*)d_in[base + 12];
    const float* vw2 = (const float*)d_in[base + 13];
    const float* vb2 = (const float*)d_in[base + 14];
    const float* vbn2g = (const float*)d_in[base + 15];
    const float* vbn2b = (const float*)d_in[base + 16];

    int N = in_sizes[0] / HD;
    int E = in_sizes[1] / 2;
    float* out = (float*)d_out;

    float *p_agg, *p_t1, *p_t2, *p_vz, *p_vt1, *p_vt2, *p_vf;
    float *p_bnA, *p_bnC, *p_bnA2, *p_bnC2;
    cudaGetSymbolAddress((void**)&p_agg, g_agg);
    cudaGetSymbolAddress((void**)&p_t1, g_t1);
    cudaGetSymbolAddress((void**)&p_t2, g_t2);
    cudaGetSymbolAddress((void**)&p_vz, g_vz);
    cudaGetSymbolAddress((void**)&p_vt1, g_vt1);
    cudaGetSymbolAddress((void**)&p_vt2, g_vt2);
    cudaGetSymbolAddress((void**)&p_vf, g_vf);
    cudaGetSymbolAddress((void**)&p_bnA, g_bnA);
    cudaGetSymbolAddress((void**)&p_bnC, g_bnC);
    cudaGetSymbolAddress((void**)&p_bnA2, g_bnA2);
    cudaGetSymbolAddress((void**)&p_bnC2, g_bnC2);

    int gN  = (N + 255) / 256;
    int gN4 = (N * (HD / 4) + 255) / 256;
    int gEt = (E + 255) / 256;
    int gNw = (N * 32 + 255) / 256;
    int gG = (NG * HD + 255) / 256;
    int gM = (N + TBM - 1) / TBM;
    int gV = (NG + TBM - 1) / TBM;
    int NB = (N + 1023) / 1024;

    // ---- build CSR once (graph static across layers) ----
    k_zero_deg<<<gN, 256>>>(N);
    k_hist<<<gEt, 256>>>(ei, E);
    k_scan1<<<NB, 256>>>(N);
    k_scan2<<<1, 128>>>(NB);
    k_scan3<<<gN, 256>>>(N);
    k_fill<<<gEt, 256>>>(ei, E);

    k_init_vf<<<gG, 256>>>(vn_emb);

    for (int i = 0; i < 3; i++) {
        const float* src = (i == 0) ? x : p_t2;
        k_compute_h<<<gN4, 256>>>(src, batch, i > 0 ? 1 : 0, N);
        k_gather<<<gNw, 256>>>(N);        // g_agg = z = h + sum (pure gather)

        mma_gemm<<<dim3(gM, HD2 / TBN), 256>>>(
            p_agg, conv_w1 + (size_t)i * HD * HD2, conv_b1 + i * HD2,
            p_t1, N, HD2, HD, 0);
        k_finalize<<<1, HD2>>>(conv_bn_g + i * HD2, conv_bn_b + i * HD2,
                               HD2, 1.0f / N, p_bnA, p_bnC);

        mma_gemm<<<dim3(gM, HD / TBN), 256>>>(
            p_t1, conv_w2 + (size_t)i * HD2 * HD, conv_b2 + i * HD,
            p_t2, N, HD, HD2, 1);
        k_finalize<<<1, HD>>>(bn_g + i * HD, bn_b + i * HD,
                              HD, 1.0f / N, p_bnA2, p_bnC2);

        if (i == 2) {
            k_bn_act<<<gN4, 256>>>(p_t2, N, HD, 0, p_bnA2, p_bnC2, out);
        }

        if (i == 1) {
            k_zero_pool<<<gG, 256>>>();
            k_pool_scatter<<<gNw, 256>>>(p_t2, batch, 1, 0, N);
            k_vz<<<gG, 256>>>();

            mma_gemm<<<dim3(gV, HD2 / TBN), 256>>>(p_vz, vw1, vb1, p_vt1,
                                                   NG, HD2, HD, 0);
            k_finalize<<<1, HD2>>>(vbn1g, vbn1b, HD2, 1.0f / NG, p_bnA, p_bnC);

            mma_gemm<<<dim3(gV, HD / TBN), 256>>>(p_vt1, vw2, vb2, p_vt2,
                                                  NG, HD, HD2, 1);
            k_finalize<<<1, HD>>>(vbn2g, vbn2b, HD, 1.0f / NG, p_bnA, p_bnC);
            k_bn_act<<<(NG * HD / 4 + 255) / 256, 256>>>(
                p_vt2, NG, HD, 1, p_bnA, p_bnC, p_vf);
        }
    }

    k_zero_pool<<<gG, 256>>>();
    k_pool_scatter<<<gNw, 256>>>(p_t2, batch, 0, 1, N);
    k_readout<<<gG, 256>>>(out + (size_t)N * HD);
    k_copy_vf<<<gG, 256>>>(out + (size_t)N * HD + NG * HD);
}

// round 10
// speedup vs baseline: 1.5666x; 1.1172x over previous
#include <cuda_runtime.h>
#include <cstdint>

#define HD   128
#define HD2  256
#define NMAX 100000
#define EMAX 1600000
#define NG   512
#define EPS  1e-5f

// ---------------- scratch (static device globals; no allocs) ----------------
__device__ float g_h[(size_t)NMAX * HD];
__device__ float g_agg[(size_t)NMAX * HD];
__device__ float g_t1[(size_t)NMAX * HD2];
__device__ float g_t2[(size_t)NMAX * HD];
__device__ float g_vf[NG * HD];
__device__ float g_vz[NG * HD];
__device__ float g_vt1[NG * HD2];
__device__ float g_vt2[NG * HD];
__device__ float g_pool[NG * HD];
__device__ float g_cnt[NG];
__device__ float g_sum[HD2];     // zero-init at load; k_finalize re-zeros after read
__device__ float g_sumsq[HD2];
__device__ float g_bnA[HD2];
__device__ float g_bnC[HD2];
__device__ float g_bnA2[HD];
__device__ float g_bnC2[HD];
// CSR build
__device__ int g_deg[NMAX];
__device__ int g_rowptr[NMAX];
__device__ int g_pos[NMAX];
__device__ int g_bsum[128];
__device__ int g_boff[128];
__device__ int g_eidx[EMAX];

__device__ __forceinline__ void red_add_v4(float* p, float4 v) {
    asm volatile("red.global.add.v4.f32 [%0], {%1, %2, %3, %4};"
                 :: "l"(p), "f"(v.x), "f"(v.y), "f"(v.z), "f"(v.w)
                 : "memory");
}

__device__ __forceinline__ float f2tf32(float x) {
    uint32_t y;
    asm("cvt.rna.tf32.f32 %0, %1;" : "=r"(y) : "f"(x));
    return __uint_as_float(y);
}

// ---------------- CSR build ----------------

__global__ void k_zero_deg(int N) {
    int i = blockIdx.x * blockDim.x + threadIdx.x;
    if (i < N) g_deg[i] = 0;
}

__global__ void k_hist(const int* __restrict__ ei, int E) {
    int e = blockIdx.x * blockDim.x + threadIdx.x;
    if (e < E) atomicAdd(&g_deg[ei[(size_t)E + e]], 1);
}

__global__ void k_scan1(int N) {
    __shared__ int ts[256];
    int b = blockIdx.x, t = threadIdx.x;
    int base = b * 1024 + t * 4;
    int v0 = (base + 0 < N) ? g_deg[base + 0] : 0;
    int v1 = (base + 1 < N) ? g_deg[base + 1] : 0;
    int v2 = (base + 2 < N) ? g_deg[base + 2] : 0;
    int v3 = (base + 3 < N) ? g_deg[base + 3] : 0;
    int s = v0 + v1 + v2 + v3;
    ts[t] = s;
    __syncthreads();
    for (int off = 1; off < 256; off <<= 1) {
        int x = (t >= off) ? ts[t - off] : 0;
        __syncthreads();
        ts[t] += x;
        __syncthreads();
    }
    int excl = ts[t] - s;
    if (base + 0 < N) g_rowptr[base + 0] = excl; excl += v0;
    if (base + 1 < N) g_rowptr[base + 1] = excl; excl += v1;
    if (base + 2 < N) g_rowptr[base + 2] = excl; excl += v2;
    if (base + 3 < N) g_rowptr[base + 3] = excl;
    if (t == 255) g_bsum[b] = ts[255];
}

__global__ void k_scan2(int NB) {
    __shared__ int bs[128];
    int t = threadIdx.x;
    int v = (t < NB) ? g_bsum[t] : 0;
    bs[t] = v;
    __syncthreads();
    for (int off = 1; off < 128; off <<= 1) {
        int x = (t >= off) ? bs[t - off] : 0;
        __syncthreads();
        bs[t] += x;
        __syncthreads();
    }
    if (t < NB) g_boff[t] = bs[t] - v;
}

__global__ void k_scan3(int N) {
    int i = blockIdx.x * blockDim.x + threadIdx.x;
    if (i < N) {
        int r = g_rowptr[i] + g_boff[i >> 10];
        g_rowptr[i] = r;
        g_pos[i] = r;
    }
}

__global__ void k_fill(const int* __restrict__ ei, int E) {
    int e = blockIdx.x * blockDim.x + threadIdx.x;
    if (e >= E) return;
    int s = ei[e];
    int d = ei[(size_t)E + e];
    int p = atomicAdd(&g_pos[d], 1);
    g_eidx[p] = s;
}

// ---------------- per-layer kernels ----------------

__global__ void k_init_vf(const float* __restrict__ vn_emb) {
    int i = blockIdx.x * blockDim.x + threadIdx.x;
    if (i < NG * HD) g_vf[i] = vn_emb[i & (HD - 1)];
}

__global__ void k_compute_h(const float* __restrict__ src,
                            const int* __restrict__ batch,
                            int mode, int N) {
    int idx = blockIdx.x * blockDim.x + threadIdx.x;
    int total = N * (HD / 4);
    if (idx >= total) return;
    int row = idx >> 5;
    int c4  = (idx & 31) << 2;
    float4 v = *(const float4*)&src[(size_t)row * HD + c4];
    if (mode) {
        float4 a = *(const float4*)&g_bnA2[c4];
        float4 c = *(const float4*)&g_bnC2[c4];
        v.x = fmaxf(fmaf(v.x, a.x, c.x), 0.f);
        v.y = fmaxf(fmaf(v.y, a.y, c.y), 0.f);
        v.z = fmaxf(fmaf(v.z, a.z, c.z), 0.f);
        v.w = fmaxf(fmaf(v.w, a.w, c.w), 0.f);
        int g = batch[row];
        float4 u = *(const float4*)&g_vf[g * HD + c4];
        v.x += u.x; v.y += u.y; v.z += u.z; v.w += u.w;
    }
    *(float4*)&g_h[(size_t)row * HD + c4] = v;
}

// warp per node: z[n] = h[n] + sum_in h[src]
__global__ void k_gather(int N) {
    int warp = (blockIdx.x * blockDim.x + threadIdx.x) >> 5;
    int lane = threadIdx.x & 31;
    if (warp >= N) return;
    int c4 = lane * 4;
    float4 acc = *(const float4*)&g_h[(size_t)warp * HD + c4];
    int j = g_rowptr[warp];
    int end = j + g_deg[warp];
    for (; j + 4 <= end; j += 4) {
        int s0 = g_eidx[j], s1 = g_eidx[j + 1];
        int s2 = g_eidx[j + 2], s3 = g_eidx[j + 3];
        float4 a = *(const float4*)&g_h[(size_t)s0 * HD + c4];
        float4 b = *(const float4*)&g_h[(size_t)s1 * HD + c4];
        float4 c = *(const float4*)&g_h[(size_t)s2 * HD + c4];
        float4 d = *(const float4*)&g_h[(size_t)s3 * HD + c4];
        acc.x += a.x + b.x + c.x + d.x;
        acc.y += a.y + b.y + c.y + d.y;
        acc.z += a.z + b.z + c.z + d.z;
        acc.w += a.w + b.w + c.w + d.w;
    }
    for (; j < end; j++) {
        int s = g_eidx[j];
        float4 a = *(const float4*)&g_h[(size_t)s * HD + c4];
        acc.x += a.x; acc.y += a.y; acc.z += a.z; acc.w += a.w;
    }
    *(float4*)&g_agg[(size_t)warp * HD + c4] = acc;
}

// ------ 3xTF32 GEMM, double-buffered smem, reg-staged pipeline --------------
#define TBM 128
#define TBN 128
#define TBK 16
#define AS_STRIDE 20
#define BS_STRIDE 136
#define AS_PLANE (TBM * AS_STRIDE)          // 2560 floats
#define BS_PLANE (TBK * BS_STRIDE)          // 2176 floats
// layout (floats): AsH[2] | AsL[2] | BsH[2] | BsL[2] | sSum[128] | sSS[128]
#define OFF_ASL (2 * AS_PLANE)              // 5120
#define OFF_BSH (4 * AS_PLANE)              // 10240
#define OFF_BSL (OFF_BSH + 2 * BS_PLANE)    // 14592
#define OFF_SSUM (OFF_BSL + 2 * BS_PLANE)   // 18944
#define OFF_SSS  (OFF_SSUM + TBN)           // 19072
#define SMEM_FLOATS (OFF_SSS + TBN)         // 19200
#define SMEM_BYTES (SMEM_FLOATS * 4)        // 76800

__global__ __launch_bounds__(256) void mma_gemm(
    const float* __restrict__ A, const float* __restrict__ B,
    const float* __restrict__ bias, float* __restrict__ C,
    int M, int N, int K, int bnOnA)
{
    extern __shared__ float sm[];
    float* sSum = sm + OFF_SSUM;
    float* sSS  = sm + OFF_SSS;

    int tid = threadIdx.x;
    int lane = tid & 31;
    int warp = tid >> 5;
    int bRow = blockIdx.x * TBM;
    int bCol = blockIdx.y * TBN;
    int warpRow = (warp & 3) * 32;
    int warpCol = (warp >> 2) * 64;

    if (tid < TBN) { sSum[tid] = 0.f; sSS[tid] = 0.f; }

    // per-thread load coords
    int aSlot0 = tid, aSlot1 = tid + 256;
    int ar0 = aSlot0 >> 2, ac0 = (aSlot0 & 3) << 2;
    int ar1 = aSlot1 >> 2, ac1 = (aSlot1 & 3) << 2;
    int br0 = aSlot0 >> 5, bc0 = (aSlot0 & 31) << 2;
    int br1 = aSlot1 >> 5, bc1 = (aSlot1 & 31) << 2;
    int gA0 = bRow + ar0, gA1 = bRow + ar1;

    float acc[2][8][4];
#pragma unroll
    for (int rt = 0; rt < 2; rt++)
#pragma unroll
        for (int ct = 0; ct < 8; ct++)
#pragma unroll
            for (int i = 0; i < 4; i++) acc[rt][ct][i] = 0.f;

    float4 aReg0, aReg1, bReg0, bReg1;
#define LOAD_TILE(k0)                                                         \
    do {                                                                      \
        aReg0 = (gA0 < M) ? *(const float4*)&A[(size_t)gA0 * K + (k0) + ac0]  \
                          : make_float4(0.f, 0.f, 0.f, 0.f);                  \
        aReg1 = (gA1 < M) ? *(const float4*)&A[(size_t)gA1 * K + (k0) + ac1]  \
                          : make_float4(0.f, 0.f, 0.f, 0.f);                  \
        bReg0 = *(const float4*)&B[(size_t)((k0) + br0) * N + bCol + bc0];    \
        bReg1 = *(const float4*)&B[(size_t)((k0) + br1) * N + bCol + bc1];    \
    } while (0)

#define SPLIT4(v, h, l)                                                       \
    do {                                                                      \
        h.x = f2tf32(v.x); l.x = f2tf32(v.x - h.x);                           \
        h.y = f2tf32(v.y); l.y = f2tf32(v.y - h.y);                           \
        h.z = f2tf32(v.z); l.z = f2tf32(v.z - h.z);                           \
        h.w = f2tf32(v.w); l.w = f2tf32(v.w - h.w);                           \
    } while (0)

    int nk = K / TBK;
    LOAD_TILE(0);

    for (int kt = 0; kt < nk; kt++) {
        int k0 = kt * TBK;
        int cur = kt & 1;
        float* AsH = sm + cur * AS_PLANE;
        float* AsL = sm + OFF_ASL + cur * AS_PLANE;
        float* BsH = sm + OFF_BSH + cur * BS_PLANE;
        float* BsL = sm + OFF_BSL + cur * BS_PLANE;

        // ---- convert + store staged regs into smem stage cur ----
        {
            float4 v = aReg0;
            if (bnOnA) {
                float4 ba = *(const float4*)&g_bnA[k0 + ac0];
                float4 bc = *(const float4*)&g_bnC[k0 + ac0];
                v.x = fmaxf(fmaf(v.x, ba.x, bc.x), 0.f);
                v.y = fmaxf(fmaf(v.y, ba.y, bc.y), 0.f);
                v.z = fmaxf(fmaf(v.z, ba.z, bc.z), 0.f);
                v.w = fmaxf(fmaf(v.w, ba.w, bc.w), 0.f);
            }
            float4 h, l;
            SPLIT4(v, h, l);
            *(float4*)&AsH[ar0 * AS_STRIDE + ac0] = h;
            *(float4*)&AsL[ar0 * AS_STRIDE + ac0] = l;

            v = aReg1;
            if (bnOnA) {
                float4 ba = *(const float4*)&g_bnA[k0 + ac1];
                float4 bc = *(const float4*)&g_bnC[k0 + ac1];
                v.x = fmaxf(fmaf(v.x, ba.x, bc.x), 0.f);
                v.y = fmaxf(fmaf(v.y, ba.y, bc.y), 0.f);
                v.z = fmaxf(fmaf(v.z, ba.z, bc.z), 0.f);
                v.w = fmaxf(fmaf(v.w, ba.w, bc.w), 0.f);
            }
            SPLIT4(v, h, l);
            *(float4*)&AsH[ar1 * AS_STRIDE + ac1] = h;
            *(float4*)&AsL[ar1 * AS_STRIDE + ac1] = l;

            SPLIT4(bReg0, h, l);
            *(float4*)&BsH[br0 * BS_STRIDE + bc0] = h;
            *(float4*)&BsL[br0 * BS_STRIDE + bc0] = l;
            SPLIT4(bReg1, h, l);
            *(float4*)&BsH[br1 * BS_STRIDE + bc1] = h;
            *(float4*)&BsL[br1 * BS_STRIDE + bc1] = l;
        }
        __syncthreads();

        // ---- issue global loads for next tile (latency hidden by mma) ----
        if (kt + 1 < nk) LOAD_TILE((kt + 1) * TBK);

        // ---- mma over stage cur ----
#pragma unroll
        for (int ks = 0; ks < 2; ks++) {
            int kc = ks * 8 + (lane & 3);
            uint32_t aH[2][4], aL[2][4];
#pragma unroll
            for (int rt = 0; rt < 2; rt++) {
                int r = warpRow + rt * 16 + (lane >> 2);
                aH[rt][0] = __float_as_uint(AsH[r * AS_STRIDE + kc]);
                aH[rt][1] = __float_as_uint(AsH[(r + 8) * AS_STRIDE + kc]);
                aH[rt][2] = __float_as_uint(AsH[r * AS_STRIDE + kc + 4]);
                aH[rt][3] = __float_as_uint(AsH[(r + 8) * AS_STRIDE + kc + 4]);
                aL[rt][0] = __float_as_uint(AsL[r * AS_STRIDE + kc]);
                aL[rt][1] = __float_as_uint(AsL[(r + 8) * AS_STRIDE + kc]);
                aL[rt][2] = __float_as_uint(AsL[r * AS_STRIDE + kc + 4]);
                aL[rt][3] = __float_as_uint(AsL[(r + 8) * AS_STRIDE + kc + 4]);
            }
#pragma unroll
            for (int ct = 0; ct < 8; ct++) {
                int c = warpCol + ct * 8 + (lane >> 2);
                uint32_t bH0 = __float_as_uint(BsH[kc * BS_STRIDE + c]);
                uint32_t bH1 = __float_as_uint(BsH[(kc + 4) * BS_STRIDE + c]);
                uint32_t bL0 = __float_as_uint(BsL[kc * BS_STRIDE + c]);
                uint32_t bL1 = __float_as_uint(BsL[(kc + 4) * BS_STRIDE + c]);
#pragma unroll
                for (int rt = 0; rt < 2; rt++) {
#define MMA(A0,A1,A2,A3,B0,B1)                                                \
                    asm volatile(                                             \
                        "mma.sync.aligned.m16n8k8.row.col.f32.tf32.tf32.f32 " \
                        "{%0,%1,%2,%3}, {%4,%5,%6,%7}, {%8,%9}, {%0,%1,%2,%3};" \
                        : "+f"(acc[rt][ct][0]), "+f"(acc[rt][ct][1]),         \
                          "+f"(acc[rt][ct][2]), "+f"(acc[rt][ct][3])          \
                        : "r"(A0), "r"(A1), "r"(A2), "r"(A3),                 \
                          "r"(B0), "r"(B1))
                    MMA(aL[rt][0], aL[rt][1], aL[rt][2], aL[rt][3], bH0, bH1);
                    MMA(aH[rt][0], aH[rt][1], aH[rt][2], aH[rt][3], bL0, bL1);
                    MMA(aH[rt][0], aH[rt][1], aH[rt][2], aH[rt][3], bH0, bH1);
#undef MMA
                }
            }
        }
        __syncthreads();
    }
#undef LOAD_TILE
#undef SPLIT4

    // ---- epilogue: bias, store, fused column stats ----
#pragma unroll
    for (int ct = 0; ct < 8; ct++) {
        int j = warpCol + ct * 8 + 2 * (lane & 3);
        float b0v = __ldg(&bias[bCol + j]);
        float b1v = __ldg(&bias[bCol + j + 1]);
#pragma unroll
        for (int rt = 0; rt < 2; rt++) {
            acc[rt][ct][0] += b0v; acc[rt][ct][1] += b1v;
            acc[rt][ct][2] += b0v; acc[rt][ct][3] += b1v;
        }
    }
#pragma unroll
    for (int rt = 0; rt < 2; rt++) {
        int r0 = bRow + warpRow + rt * 16 + (lane >> 2);
        int r1 = r0 + 8;
#pragma unroll
        for (int ct = 0; ct < 8; ct++) {
            int j = bCol + warpCol + ct * 8 + 2 * (lane & 3);
            if (r0 < M) *(float2*)&C[(size_t)r0 * N + j] =
                make_float2(acc[rt][ct][0], acc[rt][ct][1]);
            if (r1 < M) *(float2*)&C[(size_t)r1 * N + j] =
                make_float2(acc[rt][ct][2], acc[rt][ct][3]);
        }
    }
#pragma unroll
    for (int ct = 0; ct < 8; ct++) {
        float s0 = 0.f, q0 = 0.f, s1 = 0.f, q1 = 0.f;
#pragma unroll
        for (int rt = 0; rt < 2; rt++) {
            int r0 = bRow + warpRow + rt * 16 + (lane >> 2);
            int r1 = r0 + 8;
            if (r0 < M) {
                float v = acc[rt][ct][0]; s0 += v; q0 += v * v;
                v = acc[rt][ct][1]; s1 += v; q1 += v * v;
            }
            if (r1 < M) {
                float v = acc[rt][ct][2]; s0 += v; q0 += v * v;
                v = acc[rt][ct][3]; s1 += v; q1 += v * v;
            }
        }
#pragma unroll
        for (int m = 4; m < 32; m <<= 1) {
            s0 += __shfl_xor_sync(0xFFFFFFFF, s0, m);
            q0 += __shfl_xor_sync(0xFFFFFFFF, q0, m);
            s1 += __shfl_xor_sync(0xFFFFFFFF, s1, m);
            q1 += __shfl_xor_sync(0xFFFFFFFF, q1, m);
        }
        if ((lane >> 2) == 0) {
            int j = warpCol + ct * 8 + 2 * (lane & 3);
            atomicAdd(&sSum[j], s0); atomicAdd(&sSS[j], q0);
            atomicAdd(&sSum[j + 1], s1); atomicAdd(&sSS[j + 1], q1);
        }
    }
    __syncthreads();
    if (tid < TBN) {
        atomicAdd(&g_sum[bCol + tid], sSum[tid]);
        atomicAdd(&g_sumsq[bCol + tid], sSS[tid]);
    }
}

// reads stats, computes scale/shift, re-zeros stats for the next GEMM
__global__ void k_finalize(const float* __restrict__ gamma,
                           const float* __restrict__ beta,
                           int C, float invM,
                           float* __restrict__ outA, float* __restrict__ outC) {
    int t = threadIdx.x;
    if (t >= C) return;
    float mean = g_sum[t] * invM;
    float var = g_sumsq[t] * invM - mean * mean;
    float r = rsqrtf(var + EPS);
    float a = gamma[t] * r;
    outA[t] = a;
    outC[t] = beta[t] - mean * a;
    g_sum[t] = 0.f;
    g_sumsq[t] = 0.f;
}

__global__ void k_bn_act(const float* __restrict__ X, int M, int C, int doRelu,
                         const float* __restrict__ bnA, const float* __restrict__ bnC,
                         float* __restrict__ dst1) {
    int idx = blockIdx.x * blockDim.x + threadIdx.x;
    int total = M * C / 4;
    if (idx >= total) return;
    size_t off = (size_t)idx * 4;
    int col = (int)(off % C);
    float4 v = *(const float4*)&X[off];
    float4 a = *(const float4*)&bnA[col];
    float4 c = *(const float4*)&bnC[col];
    float4 y;
    y.x = fmaf(v.x, a.x, c.x);
    y.y = fmaf(v.y, a.y, c.y);
    y.z = fmaf(v.z, a.z, c.z);
    y.w = fmaf(v.w, a.w, c.w);
    if (doRelu) {
        y.x = fmaxf(y.x, 0.f); y.y = fmaxf(y.y, 0.f);
        y.z = fmaxf(y.z, 0.f); y.w = fmaxf(y.w, 0.f);
    }
    *(float4*)&dst1[off] = y;
}

__global__ void k_zero_pool() {
    int i = blockIdx.x * blockDim.x + threadIdx.x;
    if (i < NG * HD) g_pool[i] = 0.f;
    if (i < NG) g_cnt[i] = 0.f;
}

__global__ void k_pool_scatter(const float* __restrict__ X,
                               const int* __restrict__ batch,
                               int doRelu, int addCounts, int N) {
    int warp = (blockIdx.x * blockDim.x + threadIdx.x) >> 5;
    int lane = threadIdx.x & 31;
    if (warp >= N) return;
    int g = batch[warp];
    int c4 = lane * 4;
    float4 v = *(const float4*)&X[(size_t)warp * HD + c4];
    float4 a = *(const float4*)&g_bnA2[c4];
    float4 c = *(const float4*)&g_bnC2[c4];
    float4 y;
    y.x = fmaf(v.x, a.x, c.x);
    y.y = fmaf(v.y, a.y, c.y);
    y.z = fmaf(v.z, a.z, c.z);
    y.w = fmaf(v.w, a.w, c.w);
    if (doRelu) {
        y.x = fmaxf(y.x, 0.f); y.y = fmaxf(y.y, 0.f);
        y.z = fmaxf(y.z, 0.f); y.w = fmaxf(y.w, 0.f);
    }
    red_add_v4(&g_pool[g * HD + c4], y);
    if (addCounts && lane == 0) atomicAdd(&g_cnt[g], 1.f);
}

__global__ void k_vz() {
    int i = blockIdx.x * blockDim.x + threadIdx.x;
    if (i < NG * HD) g_vz[i] = g_pool[i] + g_vf[i];
}

__global__ void k_readout(float* __restrict__ out) {
    int i = blockIdx.x * blockDim.x + threadIdx.x;
    if (i < NG * HD) out[i] = g_pool[i] / fmaxf(g_cnt[i >> 7], 1.f);
}

__global__ void k_copy_vf(float* __restrict__ out) {
    int i = blockIdx.x * blockDim.x + threadIdx.x;
    if (i < NG * HD) out[i] = g_vf[i];
}

// ---------------- host ----------------
extern "C" void kernel_launch(void* const* d_in, const int* in_sizes, int n_in,
                              void* d_out, int out_size) {
    const float* x = (const float*)d_in[0];
    const int* ei = (const int*)d_in[1];
    const int* batch = (const int*)d_in[2];
    int base = 3;
    if (n_in > 3 && in_sizes[3] <= 2) base = 4;
    const float* conv_w1 = (const float*)d_in[base + 0];
    const float* conv_b1 = (const float*)d_in[base + 1];
    const float* conv_bn_g = (const float*)d_in[base + 2];
    const float* conv_bn_b = (const float*)d_in[base + 3];
    const float* conv_w2 = (const float*)d_in[base + 4];
    const float* conv_b2 = (const float*)d_in[base + 5];
    const float* bn_g = (const float*)d_in[base + 6];
    const float* bn_b = (const float*)d_in[base + 7];
    const float* vn_emb = (const float*)d_in[base + 8];
    const float* vw1 = (const float*)d_in[base + 9];
    const float* vb1 = (const float*)d_in[base + 10];
    const float* vbn1g = (const float*)d_in[base + 11];
    const float* vbn1b = (const float*)d_in[base + 12];
    const float* vw2 = (const float*)d_in[base + 13];
    const float* vb2 = (const float*)d_in[base + 14];
    const float* vbn2g = (const float*)d_in[base + 15];
    const float* vbn2b = (const float*)d_in[base + 16];

    int N = in_sizes[0] / HD;
    int E = in_sizes[1] / 2;
    float* out = (float*)d_out;

    static int smemSet = 0;
    if (!smemSet) {
        cudaFuncSetAttribute(mma_gemm, cudaFuncAttributeMaxDynamicSharedMemorySize,
                             SMEM_BYTES);
        smemSet = 1;
    }

    float *p_agg, *p_t1, *p_t2, *p_vz, *p_vt1, *p_vt2, *p_vf;
    float *p_bnA, *p_bnC, *p_bnA2, *p_bnC2;
    cudaGetSymbolAddress((void**)&p_agg, g_agg);
    cudaGetSymbolAddress((void**)&p_t1, g_t1);
    cudaGetSymbolAddress((void**)&p_t2, g_t2);
    cudaGetSymbolAddress((void**)&p_vz, g_vz);
    cudaGetSymbolAddress((void**)&p_vt1, g_vt1);
    cudaGetSymbolAddress((void**)&p_vt2, g_vt2);
    cudaGetSymbolAddress((void**)&p_vf, g_vf);
    cudaGetSymbolAddress((void**)&p_bnA, g_bnA);
    cudaGetSymbolAddress((void**)&p_bnC, g_bnC);
    cudaGetSymbolAddress((void**)&p_bnA2, g_bnA2);
    cudaGetSymbolAddress((void**)&p_bnC2, g_bnC2);

    int gN  = (N + 255) / 256;
    int gN4 = (N * (HD / 4) + 255) / 256;
    int gEt = (E + 255) / 256;
    int gNw = (N * 32 + 255) / 256;
    int gG = (NG * HD + 255) / 256;
    int gM = (N + TBM - 1) / TBM;
    int gV = (NG + TBM - 1) / TBM;
    int NB = (N + 1023) / 1024;

    // ---- build CSR once ----
    k_zero_deg<<<gN, 256>>>(N);
    k_hist<<<gEt, 256>>>(ei, E);
    k_scan1<<<NB, 256>>>(N);
    k_scan2<<<1, 128>>>(NB);
    k_scan3<<<gN, 256>>>(N);
    k_fill<<<gEt, 256>>>(ei, E);

    k_init_vf<<<gG, 256>>>(vn_emb);

    for (int i = 0; i < 3; i++) {
        const float* src = (i == 0) ? x : p_t2;
        k_compute_h<<<gN4, 256>>>(src, batch, i > 0 ? 1 : 0, N);
        k_gather<<<gNw, 256>>>(N);

        mma_gemm<<<dim3(gM, HD2 / TBN), 256, SMEM_BYTES>>>(
            p_agg, conv_w1 + (size_t)i * HD * HD2, conv_b1 + i * HD2,
            p_t1, N, HD2, HD, 0);
        k_finalize<<<1, HD2>>>(conv_bn_g + i * HD2, conv_bn_b + i * HD2,
                               HD2, 1.0f / N, p_bnA, p_bnC);

        mma_gemm<<<dim3(gM, HD / TBN), 256, SMEM_BYTES>>>(
            p_t1, conv_w2 + (size_t)i * HD2 * HD, conv_b2 + i * HD,
            p_t2, N, HD, HD2, 1);
        k_finalize<<<1, HD>>>(bn_g + i * HD, bn_b + i * HD,
                              HD, 1.0f / N, p_bnA2, p_bnC2);

        if (i == 2) {
            k_bn_act<<<gN4, 256>>>(p_t2, N, HD, 0, p_bnA2, p_bnC2, out);
        }

        if (i == 1) {
            k_zero_pool<<<gG, 256>>>();
            k_pool_scatter<<<gNw, 256>>>(p_t2, batch, 1, 0, N);
            k_vz<<<gG, 256>>>();

            mma_gemm<<<dim3(gV, HD2 / TBN), 256, SMEM_BYTES>>>(
                p_vz, vw1, vb1, p_vt1, NG, HD2, HD, 0);
            k_finalize<<<1, HD2>>>(vbn1g, vbn1b, HD2, 1.0f / NG, p_bnA, p_bnC);

            mma_gemm<<<dim3(gV, HD / TBN), 256, SMEM_BYTES>>>(
                p_vt1, vw2, vb2, p_vt2, NG, HD, HD2, 1);
            k_finalize<<<1, HD>>>(vbn2g, vbn2b, HD, 1.0f / NG, p_bnA, p_bnC);
            k_bn_act<<<(NG * HD / 4 + 255) / 256, 256>>>(
                p_vt2, NG, HD, 1, p_bnA, p_bnC, p_vf);
        }
    }

    k_zero_pool<<<gG, 256>>>();
    k_pool_scatter<<<gNw, 256>>>(p_t2, batch, 0, 1, N);
    k_readout<<<gG, 256>>>(out + (size_t)N * HD);
    k_copy_vf<<<gG, 256>>>(out + (size_t)N * HD + NG * HD);
}

// round 11
// speedup vs baseline: 2.0861x; 1.3316x over previous
#include <cuda_runtime.h>
#include <cuda_bf16.h>
#include <cstdint>

#define HD   128
#define HD2  256
#define NMAX 100000
#define EMAX 1600000
#define NG   512
#define EPS  1e-5f

// ---------------- scratch (static device globals; no allocs) ----------------
__device__ float g_h[(size_t)NMAX * HD];
__device__ float g_agg[(size_t)NMAX * HD];
__device__ float g_t1[(size_t)NMAX * HD2];
__device__ float g_t2[(size_t)NMAX * HD];
__device__ float g_vf[NG * HD];
__device__ float g_vz[NG * HD];
__device__ float g_vt1[NG * HD2];
__device__ float g_vt2[NG * HD];
__device__ float g_pool[NG * HD];
__device__ float g_cnt[NG];
__device__ float g_sum[HD2];     // zero-init at load; k_finalize re-zeros after read
__device__ float g_sumsq[HD2];
__device__ float g_bnA[HD2];
__device__ float g_bnC[HD2];
__device__ float g_bnA2[HD];
__device__ float g_bnC2[HD];
// CSR build
__device__ int g_deg[NMAX];
__device__ int g_rowptr[NMAX];
__device__ int g_pos[NMAX];
__device__ int g_bsum[128];
__device__ int g_boff[128];
__device__ int g_eidx[EMAX];

__device__ __forceinline__ void red_add_v4(float* p, float4 v) {
    asm volatile("red.global.add.v4.f32 [%0], {%1, %2, %3, %4};"
                 :: "l"(p), "f"(v.x), "f"(v.y), "f"(v.z), "f"(v.w)
                 : "memory");
}

// ---------------- CSR build ----------------

__global__ void k_zero_deg(int N) {
    int i = blockIdx.x * blockDim.x + threadIdx.x;
    if (i < N) g_deg[i] = 0;
}

__global__ void k_hist(const int* __restrict__ ei, int E) {
    int e = blockIdx.x * blockDim.x + threadIdx.x;
    if (e < E) atomicAdd(&g_deg[ei[(size_t)E + e]], 1);
}

__global__ void k_scan1(int N) {
    __shared__ int ts[256];
    int b = blockIdx.x, t = threadIdx.x;
    int base = b * 1024 + t * 4;
    int v0 = (base + 0 < N) ? g_deg[base + 0] : 0;
    int v1 = (base + 1 < N) ? g_deg[base + 1] : 0;
    int v2 = (base + 2 < N) ? g_deg[base + 2] : 0;
    int v3 = (base + 3 < N) ? g_deg[base + 3] : 0;
    int s = v0 + v1 + v2 + v3;
    ts[t] = s;
    __syncthreads();
    for (int off = 1; off < 256; off <<= 1) {
        int x = (t >= off) ? ts[t - off] : 0;
        __syncthreads();
        ts[t] += x;
        __syncthreads();
    }
    int excl = ts[t] - s;
    if (base + 0 < N) g_rowptr[base + 0] = excl; excl += v0;
    if (base + 1 < N) g_rowptr[base + 1] = excl; excl += v1;
    if (base + 2 < N) g_rowptr[base + 2] = excl; excl += v2;
    if (base + 3 < N) g_rowptr[base + 3] = excl;
    if (t == 255) g_bsum[b] = ts[255];
}

__global__ void k_scan2(int NB) {
    __shared__ int bs[128];
    int t = threadIdx.x;
    int v = (t < NB) ? g_bsum[t] : 0;
    bs[t] = v;
    __syncthreads();
    for (int off = 1; off < 128; off <<= 1) {
        int x = (t >= off) ? bs[t - off] : 0;
        __syncthreads();
        bs[t] += x;
        __syncthreads();
    }
    if (t < NB) g_boff[t] = bs[t] - v;
}

__global__ void k_scan3(int N) {
    int i = blockIdx.x * blockDim.x + threadIdx.x;
    if (i < N) {
        int r = g_rowptr[i] + g_boff[i >> 10];
        g_rowptr[i] = r;
        g_pos[i] = r;
    }
}

__global__ void k_fill(const int* __restrict__ ei, int E) {
    int e = blockIdx.x * blockDim.x + threadIdx.x;
    if (e >= E) return;
    int s = ei[e];
    int d = ei[(size_t)E + e];
    int p = atomicAdd(&g_pos[d], 1);
    g_eidx[p] = s;
}

// ---------------- per-layer kernels ----------------

__global__ void k_init_vf(const float* __restrict__ vn_emb) {
    int i = blockIdx.x * blockDim.x + threadIdx.x;
    if (i < NG * HD) g_vf[i] = vn_emb[i & (HD - 1)];
}

__global__ void k_compute_h(const float* __restrict__ src,
                            const int* __restrict__ batch,
                            int mode, int N) {
    int idx = blockIdx.x * blockDim.x + threadIdx.x;
    int total = N * (HD / 4);
    if (idx >= total) return;
    int row = idx >> 5;
    int c4  = (idx & 31) << 2;
    float4 v = *(const float4*)&src[(size_t)row * HD + c4];
    if (mode) {
        float4 a = *(const float4*)&g_bnA2[c4];
        float4 c = *(const float4*)&g_bnC2[c4];
        v.x = fmaxf(fmaf(v.x, a.x, c.x), 0.f);
        v.y = fmaxf(fmaf(v.y, a.y, c.y), 0.f);
        v.z = fmaxf(fmaf(v.z, a.z, c.z), 0.f);
        v.w = fmaxf(fmaf(v.w, a.w, c.w), 0.f);
        int g = batch[row];
        float4 u = *(const float4*)&g_vf[g * HD + c4];
        v.x += u.x; v.y += u.y; v.z += u.z; v.w += u.w;
    }
    *(float4*)&g_h[(size_t)row * HD + c4] = v;
}

// warp per node: z[n] = h[n] + sum_in h[src]
__global__ void k_gather(int N) {
    int warp = (blockIdx.x * blockDim.x + threadIdx.x) >> 5;
    int lane = threadIdx.x & 31;
    if (warp >= N) return;
    int c4 = lane * 4;
    float4 acc = *(const float4*)&g_h[(size_t)warp * HD + c4];
    int j = g_rowptr[warp];
    int end = j + g_deg[warp];
    for (; j + 4 <= end; j += 4) {
        int s0 = g_eidx[j], s1 = g_eidx[j + 1];
        int s2 = g_eidx[j + 2], s3 = g_eidx[j + 3];
        float4 a = *(const float4*)&g_h[(size_t)s0 * HD + c4];
        float4 b = *(const float4*)&g_h[(size_t)s1 * HD + c4];
        float4 c = *(const float4*)&g_h[(size_t)s2 * HD + c4];
        float4 d = *(const float4*)&g_h[(size_t)s3 * HD + c4];
        acc.x += a.x + b.x + c.x + d.x;
        acc.y += a.y + b.y + c.y + d.y;
        acc.z += a.z + b.z + c.z + d.z;
        acc.w += a.w + b.w + c.w + d.w;
    }
    for (; j < end; j++) {
        int s = g_eidx[j];
        float4 a = *(const float4*)&g_h[(size_t)s * HD + c4];
        acc.x += a.x; acc.y += a.y; acc.z += a.z; acc.w += a.w;
    }
    *(float4*)&g_agg[(size_t)warp * HD + c4] = acc;
}

// ---- split-BF16 GEMM (3 terms: aH*bH + aL*bH + aH*bL), double-buffered ----
#define TBM 128
#define TBN 128
#define TBK 16
#define KP  9   // u32 stride per row (8 kpairs + 1 pad) — conflict-free frags

__device__ __forceinline__ uint32_t pack_bf16x2(float lo, float hi) {
    __nv_bfloat162 p = __floats2bfloat162_rn(lo, hi);  // .x = lo half
    uint32_t u;
    memcpy(&u, &p, 4);
    return u;
}

__global__ __launch_bounds__(256) void mma_gemm(
    const float* __restrict__ A, const float* __restrict__ B,
    const float* __restrict__ bias, float* __restrict__ C,
    int M, int N, int K, int bnOnA)
{
    __shared__ uint32_t AsH[2][TBM][KP];
    __shared__ uint32_t AsL[2][TBM][KP];
    __shared__ uint32_t BsH[2][TBN][KP];
    __shared__ uint32_t BsL[2][TBN][KP];
    __shared__ float sSum[TBN], sSS[TBN];

    int tid = threadIdx.x;
    int lane = tid & 31;
    int warp = tid >> 5;
    int bRow = blockIdx.x * TBM;
    int bCol = blockIdx.y * TBN;
    int warpRow = (warp & 3) * 32;
    int warpCol = (warp >> 2) * 64;

    if (tid < TBN) { sSum[tid] = 0.f; sSS[tid] = 0.f; }

    // per-thread load coords (2 slots each for A and B)
    int ar0 = tid >> 2,        ac0 = (tid & 3) << 2;
    int ar1 = (tid + 256) >> 2, ac1 = ((tid + 256) & 3) << 2;
    int br0 = tid >> 5,        bc0 = (tid & 31) << 2;
    int br1 = (tid + 256) >> 5, bc1 = ((tid + 256) & 31) << 2;
    int gA0 = bRow + ar0, gA1 = bRow + ar1;

    float acc[2][8][4];
#pragma unroll
    for (int rt = 0; rt < 2; rt++)
#pragma unroll
        for (int ct = 0; ct < 8; ct++)
#pragma unroll
            for (int i = 0; i < 4; i++) acc[rt][ct][i] = 0.f;

    float4 aReg0, aReg1, bReg0, bReg1;
#define LOAD_TILE(k0)                                                         \
    do {                                                                      \
        aReg0 = (gA0 < M) ? *(const float4*)&A[(size_t)gA0 * K + (k0) + ac0]  \
                          : make_float4(0.f, 0.f, 0.f, 0.f);                  \
        aReg1 = (gA1 < M) ? *(const float4*)&A[(size_t)gA1 * K + (k0) + ac1]  \
                          : make_float4(0.f, 0.f, 0.f, 0.f);                  \
        bReg0 = *(const float4*)&B[(size_t)((k0) + br0) * N + bCol + bc0];    \
        bReg1 = *(const float4*)&B[(size_t)((k0) + br1) * N + bCol + bc1];    \
    } while (0)

    int nk = K / TBK;
    LOAD_TILE(0);

    for (int kt = 0; kt < nk; kt++) {
        int k0 = kt * TBK;
        int cur = kt & 1;

        // ---- stage A: bn + hi/lo bf16 split, pack k-pairs ----
        {
            float4 v = aReg0;
            if (bnOnA) {
                float4 ba = *(const float4*)&g_bnA[k0 + ac0];
                float4 bc = *(const float4*)&g_bnC[k0 + ac0];
                v.x = fmaxf(fmaf(v.x, ba.x, bc.x), 0.f);
                v.y = fmaxf(fmaf(v.y, ba.y, bc.y), 0.f);
                v.z = fmaxf(fmaf(v.z, ba.z, bc.z), 0.f);
                v.w = fmaxf(fmaf(v.w, ba.w, bc.w), 0.f);
            }
            float hx = __bfloat162float(__float2bfloat16(v.x));
            float hy = __bfloat162float(__float2bfloat16(v.y));
            float hz = __bfloat162float(__float2bfloat16(v.z));
            float hw = __bfloat162float(__float2bfloat16(v.w));
            AsH[cur][ar0][(ac0 >> 1) + 0] = pack_bf16x2(hx, hy);
            AsH[cur][ar0][(ac0 >> 1) + 1] = pack_bf16x2(hz, hw);
            AsL[cur][ar0][(ac0 >> 1) + 0] = pack_bf16x2(v.x - hx, v.y - hy);
            AsL[cur][ar0][(ac0 >> 1) + 1] = pack_bf16x2(v.z - hz, v.w - hw);

            v = aReg1;
            if (bnOnA) {
                float4 ba = *(const float4*)&g_bnA[k0 + ac1];
                float4 bc = *(const float4*)&g_bnC[k0 + ac1];
                v.x = fmaxf(fmaf(v.x, ba.x, bc.x), 0.f);
                v.y = fmaxf(fmaf(v.y, ba.y, bc.y), 0.f);
                v.z = fmaxf(fmaf(v.z, ba.z, bc.z), 0.f);
                v.w = fmaxf(fmaf(v.w, ba.w, bc.w), 0.f);
            }
            hx = __bfloat162float(__float2bfloat16(v.x));
            hy = __bfloat162float(__float2bfloat16(v.y));
            hz = __bfloat162float(__float2bfloat16(v.z));
            hw = __bfloat162float(__float2bfloat16(v.w));
            AsH[cur][ar1][(ac1 >> 1) + 0] = pack_bf16x2(hx, hy);
            AsH[cur][ar1][(ac1 >> 1) + 1] = pack_bf16x2(hz, hw);
            AsL[cur][ar1][(ac1 >> 1) + 0] = pack_bf16x2(v.x - hx, v.y - hy);
            AsL[cur][ar1][(ac1 >> 1) + 1] = pack_bf16x2(v.z - hz, v.w - hw);
        }
        // ---- stage B: transpose into [n][kpair] with 16-bit stores ----
        {
            uint16_t* bh = (uint16_t*)BsH[cur];
            uint16_t* bl = (uint16_t*)BsL[cur];
            float vv[4] = {bReg0.x, bReg0.y, bReg0.z, bReg0.w};
#pragma unroll
            for (int i = 0; i < 4; i++) {
                int n = bc0 + i;
                __nv_bfloat16 h = __float2bfloat16(vv[i]);
                float hf = __bfloat162float(h);
                __nv_bfloat16 l = __float2bfloat16(vv[i] - hf);
                int idx = (n * KP + (br0 >> 1)) * 2 + (br0 & 1);
                bh[idx] = __bfloat16_as_ushort(h);
                bl[idx] = __bfloat16_as_ushort(l);
            }
            float vw[4] = {bReg1.x, bReg1.y, bReg1.z, bReg1.w};
#pragma unroll
            for (int i = 0; i < 4; i++) {
                int n = bc1 + i;
                __nv_bfloat16 h = __float2bfloat16(vw[i]);
                float hf = __bfloat162float(h);
                __nv_bfloat16 l = __float2bfloat16(vw[i] - hf);
                int idx = (n * KP + (br1 >> 1)) * 2 + (br1 & 1);
                bh[idx] = __bfloat16_as_ushort(h);
                bl[idx] = __bfloat16_as_ushort(l);
            }
        }
        __syncthreads();

        // ---- prefetch next tile into regs (hidden behind mma) ----
        if (kt + 1 < nk) LOAD_TILE((kt + 1) * TBK);

        // ---- mma over stage cur: m16n8k16 bf16, 3 terms ----
        int j = lane & 3;
        uint32_t aH[2][4], aL[2][4];
#pragma unroll
        for (int rt = 0; rt < 2; rt++) {
            int r = warpRow + rt * 16 + (lane >> 2);
            aH[rt][0] = AsH[cur][r][j];
            aH[rt][1] = AsH[cur][r + 8][j];
            aH[rt][2] = AsH[cur][r][j + 4];
            aH[rt][3] = AsH[cur][r + 8][j + 4];
            aL[rt][0] = AsL[cur][r][j];
            aL[rt][1] = AsL[cur][r + 8][j];
            aL[rt][2] = AsL[cur][r][j + 4];
            aL[rt][3] = AsL[cur][r + 8][j + 4];
        }
#pragma unroll
        for (int ct = 0; ct < 8; ct++) {
            int n = warpCol + ct * 8 + (lane >> 2);
            uint32_t bH0 = BsH[cur][n][j];
            uint32_t bH1 = BsH[cur][n][j + 4];
            uint32_t bL0 = BsL[cur][n][j];
            uint32_t bL1 = BsL[cur][n][j + 4];
#pragma unroll
            for (int rt = 0; rt < 2; rt++) {
#define MMA(A0,A1,A2,A3,B0,B1)                                                \
                asm volatile(                                                 \
                    "mma.sync.aligned.m16n8k16.row.col.f32.bf16.bf16.f32 "    \
                    "{%0,%1,%2,%3}, {%4,%5,%6,%7}, {%8,%9}, {%0,%1,%2,%3};"   \
                    : "+f"(acc[rt][ct][0]), "+f"(acc[rt][ct][1]),             \
                      "+f"(acc[rt][ct][2]), "+f"(acc[rt][ct][3])              \
                    : "r"(A0), "r"(A1), "r"(A2), "r"(A3),                     \
                      "r"(B0), "r"(B1))
                MMA(aL[rt][0], aL[rt][1], aL[rt][2], aL[rt][3], bH0, bH1);
                MMA(aH[rt][0], aH[rt][1], aH[rt][2], aH[rt][3], bL0, bL1);
                MMA(aH[rt][0], aH[rt][1], aH[rt][2], aH[rt][3], bH0, bH1);
#undef MMA
            }
        }
        __syncthreads();
    }
#undef LOAD_TILE

    // ---- epilogue: bias, store, fused column stats ----
#pragma unroll
    for (int ct = 0; ct < 8; ct++) {
        int j2 = warpCol + ct * 8 + 2 * (lane & 3);
        float b0v = __ldg(&bias[bCol + j2]);
        float b1v = __ldg(&bias[bCol + j2 + 1]);
#pragma unroll
        for (int rt = 0; rt < 2; rt++) {
            acc[rt][ct][0] += b0v; acc[rt][ct][1] += b1v;
            acc[rt][ct][2] += b0v; acc[rt][ct][3] += b1v;
        }
    }
#pragma unroll
    for (int rt = 0; rt < 2; rt++) {
        int r0 = bRow + warpRow + rt * 16 + (lane >> 2);
        int r1 = r0 + 8;
#pragma unroll
        for (int ct = 0; ct < 8; ct++) {
            int j2 = bCol + warpCol + ct * 8 + 2 * (lane & 3);
            if (r0 < M) *(float2*)&C[(size_t)r0 * N + j2] =
                make_float2(acc[rt][ct][0], acc[rt][ct][1]);
            if (r1 < M) *(float2*)&C[(size_t)r1 * N + j2] =
                make_float2(acc[rt][ct][2], acc[rt][ct][3]);
        }
    }
#pragma unroll
    for (int ct = 0; ct < 8; ct++) {
        float s0 = 0.f, q0 = 0.f, s1 = 0.f, q1 = 0.f;
#pragma unroll
        for (int rt = 0; rt < 2; rt++) {
            int r0 = bRow + warpRow + rt * 16 + (lane >> 2);
            int r1 = r0 + 8;
            if (r0 < M) {
                float v = acc[rt][ct][0]; s0 += v; q0 += v * v;
                v = acc[rt][ct][1]; s1 += v; q1 += v * v;
            }
            if (r1 < M) {
                float v = acc[rt][ct][2]; s0 += v; q0 += v * v;
                v = acc[rt][ct][3]; s1 += v; q1 += v * v;
            }
        }
#pragma unroll
        for (int m = 4; m < 32; m <<= 1) {
            s0 += __shfl_xor_sync(0xFFFFFFFF, s0, m);
            q0 += __shfl_xor_sync(0xFFFFFFFF, q0, m);
            s1 += __shfl_xor_sync(0xFFFFFFFF, s1, m);
            q1 += __shfl_xor_sync(0xFFFFFFFF, q1, m);
        }
        if ((lane >> 2) == 0) {
            int j2 = warpCol + ct * 8 + 2 * (lane & 3);
            atomicAdd(&sSum[j2], s0); atomicAdd(&sSS[j2], q0);
            atomicAdd(&sSum[j2 + 1], s1); atomicAdd(&sSS[j2 + 1], q1);
        }
    }
    __syncthreads();
    if (tid < TBN) {
        atomicAdd(&g_sum[bCol + tid], sSum[tid]);
        atomicAdd(&g_sumsq[bCol + tid], sSS[tid]);
    }
}

// reads stats, computes scale/shift, re-zeros stats for the next GEMM
__global__ void k_finalize(const float* __restrict__ gamma,
                           const float* __restrict__ beta,
                           int C, float invM,
                           float* __restrict__ outA, float* __restrict__ outC) {
    int t = threadIdx.x;
    if (t >= C) return;
    float mean = g_sum[t] * invM;
    float var = g_sumsq[t] * invM - mean * mean;
    float r = rsqrtf(var + EPS);
    float a = gamma[t] * r;
    outA[t] = a;
    outC[t] = beta[t] - mean * a;
    g_sum[t] = 0.f;
    g_sumsq[t] = 0.f;
}

__global__ void k_bn_act(const float* __restrict__ X, int M, int C, int doRelu,
                         const float* __restrict__ bnA, const float* __restrict__ bnC,
                         float* __restrict__ dst1) {
    int idx = blockIdx.x * blockDim.x + threadIdx.x;
    int total = M * C / 4;
    if (idx >= total) return;
    size_t off = (size_t)idx * 4;
    int col = (int)(off % C);
    float4 v = *(const float4*)&X[off];
    float4 a = *(const float4*)&bnA[col];
    float4 c = *(const float4*)&bnC[col];
    float4 y;
    y.x = fmaf(v.x, a.x, c.x);
    y.y = fmaf(v.y, a.y, c.y);
    y.z = fmaf(v.z, a.z, c.z);
    y.w = fmaf(v.w, a.w, c.w);
    if (doRelu) {
        y.x = fmaxf(y.x, 0.f); y.y = fmaxf(y.y, 0.f);
        y.z = fmaxf(y.z, 0.f); y.w = fmaxf(y.w, 0.f);
    }
    *(float4*)&dst1[off] = y;
}

__global__ void k_zero_pool() {
    int i = blockIdx.x * blockDim.x + threadIdx.x;
    if (i < NG * HD) g_pool[i] = 0.f;
    if (i < NG) g_cnt[i] = 0.f;
}

__global__ void k_pool_scatter(const float* __restrict__ X,
                               const int* __restrict__ batch,
                               int doRelu, int addCounts, int N) {
    int warp = (blockIdx.x * blockDim.x + threadIdx.x) >> 5;
    int lane = threadIdx.x & 31;
    if (warp >= N) return;
    int g = batch[warp];
    int c4 = lane * 4;
    float4 v = *(const float4*)&X[(size_t)warp * HD + c4];
    float4 a = *(const float4*)&g_bnA2[c4];
    float4 c = *(const float4*)&g_bnC2[c4];
    float4 y;
    y.x = fmaf(v.x, a.x, c.x);
    y.y = fmaf(v.y, a.y, c.y);
    y.z = fmaf(v.z, a.z, c.z);
    y.w = fmaf(v.w, a.w, c.w);
    if (doRelu) {
        y.x = fmaxf(y.x, 0.f); y.y = fmaxf(y.y, 0.f);
        y.z = fmaxf(y.z, 0.f); y.w = fmaxf(y.w, 0.f);
    }
    red_add_v4(&g_pool[g * HD + c4], y);
    if (addCounts && lane == 0) atomicAdd(&g_cnt[g], 1.f);
}

__global__ void k_vz() {
    int i = blockIdx.x * blockDim.x + threadIdx.x;
    if (i < NG * HD) g_vz[i] = g_pool[i] + g_vf[i];
}

__global__ void k_readout(float* __restrict__ out) {
    int i = blockIdx.x * blockDim.x + threadIdx.x;
    if (i < NG * HD) out[i] = g_pool[i] / fmaxf(g_cnt[i >> 7], 1.f);
}

__global__ void k_copy_vf(float* __restrict__ out) {
    int i = blockIdx.x * blockDim.x + threadIdx.x;
    if (i < NG * HD) out[i] = g_vf[i];
}

// ---------------- host ----------------
extern "C" void kernel_launch(void* const* d_in, const int* in_sizes, int n_in,
                              void* d_out, int out_size) {
    const float* x = (const float*)d_in[0];
    const int* ei = (const int*)d_in[1];
    const int* batch = (const int*)d_in[2];
    int base = 3;
    if (n_in > 3 && in_sizes[3] <= 2) base = 4;
    const float* conv_w1 = (const float*)d_in[base + 0];
    const float* conv_b1 = (const float*)d_in[base + 1];
    const float* conv_bn_g = (const float*)d_in[base + 2];
    const float* conv_bn_b = (const float*)d_in[base + 3];
    const float* conv_w2 = (const float*)d_in[base + 4];
    const float* conv_b2 = (const float*)d_in[base + 5];
    const float* bn_g = (const float*)d_in[base + 6];
    const float* bn_b = (const float*)d_in[base + 7];
    const float* vn_emb = (const float*)d_in[base + 8];
    const float* vw1 = (const float*)d_in[base + 9];
    const float* vb1 = (const float*)d_in[base + 10];
    const float* vbn1g = (const float*)d_in[base + 11];
    const float* vbn1b = (const float*)d_in[base + 12];
    const float* vw2 = (const float*)d_in[base + 13];
    const float* vb2 = (const float*)d_in[base + 14];
    const float* vbn2g = (const float*)d_in[base + 15];
    const float* vbn2b = (const float*)d_in[base + 16];

    int N = in_sizes[0] / HD;
    int E = in_sizes[1] / 2;
    float* out = (float*)d_out;

    float *p_agg, *p_t1, *p_t2, *p_vz, *p_vt1, *p_vt2, *p_vf;
    float *p_bnA, *p_bnC, *p_bnA2, *p_bnC2;
    cudaGetSymbolAddress((void**)&p_agg, g_agg);
    cudaGetSymbolAddress((void**)&p_t1, g_t1);
    cudaGetSymbolAddress((void**)&p_t2, g_t2);
    cudaGetSymbolAddress((void**)&p_vz, g_vz);
    cudaGetSymbolAddress((void**)&p_vt1, g_vt1);
    cudaGetSymbolAddress((void**)&p_vt2, g_vt2);
    cudaGetSymbolAddress((void**)&p_vf, g_vf);
    cudaGetSymbolAddress((void**)&p_bnA, g_bnA);
    cudaGetSymbolAddress((void**)&p_bnC, g_bnC);
    cudaGetSymbolAddress((void**)&p_bnA2, g_bnA2);
    cudaGetSymbolAddress((void**)&p_bnC2, g_bnC2);

    int gN  = (N + 255) / 256;
    int gN4 = (N * (HD / 4) + 255) / 256;
    int gEt = (E + 255) / 256;
    int gNw = (N * 32 + 255) / 256;
    int gG = (NG * HD + 255) / 256;
    int gM = (N + TBM - 1) / TBM;
    int gV = (NG + TBM - 1) / TBM;
    int NB = (N + 1023) / 1024;

    // ---- build CSR once ----
    k_zero_deg<<<gN, 256>>>(N);
    k_hist<<<gEt, 256>>>(ei, E);
    k_scan1<<<NB, 256>>>(N);
    k_scan2<<<1, 128>>>(NB);
    k_scan3<<<gN, 256>>>(N);
    k_fill<<<gEt, 256>>>(ei, E);

    k_init_vf<<<gG, 256>>>(vn_emb);

    for (int i = 0; i < 3; i++) {
        const float* src = (i == 0) ? x : p_t2;
        k_compute_h<<<gN4, 256>>>(src, batch, i > 0 ? 1 : 0, N);
        k_gather<<<gNw, 256>>>(N);

        mma_gemm<<<dim3(gM, HD2 / TBN), 256>>>(
            p_agg, conv_w1 + (size_t)i * HD * HD2, conv_b1 + i * HD2,
            p_t1, N, HD2, HD, 0);
        k_finalize<<<1, HD2>>>(conv_bn_g + i * HD2, conv_bn_b + i * HD2,
                               HD2, 1.0f / N, p_bnA, p_bnC);

        mma_gemm<<<dim3(gM, HD / TBN), 256>>>(
            p_t1, conv_w2 + (size_t)i * HD2 * HD, conv_b2 + i * HD,
            p_t2, N, HD, HD2, 1);
        k_finalize<<<1, HD>>>(bn_g + i * HD, bn_b + i * HD,
                              HD, 1.0f / N, p_bnA2, p_bnC2);

        if (i == 2) {
            k_bn_act<<<gN4, 256>>>(p_t2, N, HD, 0, p_bnA2, p_bnC2, out);
        }

        if (i == 1) {
            k_zero_pool<<<gG, 256>>>();
            k_pool_scatter<<<gNw, 256>>>(p_t2, batch, 1, 0, N);
            k_vz<<<gG, 256>>>();

            mma_gemm<<<dim3(gV, HD2 / TBN), 256>>>(
                p_vz, vw1, vb1, p_vt1, NG, HD2, HD, 0);
            k_finalize<<<1, HD2>>>(vbn1g, vbn1b, HD2, 1.0f / NG, p_bnA, p_bnC);

            mma_gemm<<<dim3(gV, HD / TBN), 256>>>(
                p_vt1, vw2, vb2, p_vt2, NG, HD, HD2, 1);
            k_finalize<<<1, HD>>>(vbn2g, vbn2b, HD, 1.0f / NG, p_bnA, p_bnC);
            k_bn_act<<<(NG * HD / 4 + 255) / 256, 256>>>(
                p_vt2, NG, HD, 1, p_bnA, p_bnC, p_vf);
        }
    }

    k_zero_pool<<<gG, 256>>>();
    k_pool_scatter<<<gNw, 256>>>(p_t2, batch, 0, 1, N);
    k_readout<<<gG, 256>>>(out + (size_t)N * HD);
    k_copy_vf<<<gG, 256>>>(out + (size_t)N * HD + NG * HD);
}

// round 12
// speedup vs baseline: 2.1353x; 1.0236x over previous
#include <cuda_runtime.h>
#include <cuda_bf16.h>
#include <cstdint>

#define HD   128
#define HD2  256
#define NMAX 100000
#define EMAX 1600000
#define NG   512
#define EPS  1e-5f

// ---------------- scratch (static device globals; no allocs) ----------------
__device__ float g_h[(size_t)NMAX * HD];
__device__ float g_agg[(size_t)NMAX * HD];
__device__ float g_t1[(size_t)NMAX * HD2];
__device__ float g_t2[(size_t)NMAX * HD];
__device__ float g_vf[NG * HD];
__device__ float g_vz[NG * HD];
__device__ float g_vt1[NG * HD2];
__device__ float g_vt2[NG * HD];
__device__ float g_pool[NG * HD];
__device__ float g_cnt[NG];
__device__ float g_sum[HD2];     // zero-init at load; k_finalize re-zeros after read
__device__ float g_sumsq[HD2];
__device__ float g_bnA[HD2];
__device__ float g_bnC[HD2];
__device__ float g_bnA2[HD];
__device__ float g_bnC2[HD];
// pre-split weights: hi/lo bf16 planes, [n][kpair] layout (mma B-fragment order)
// 8 matrices x 32768 elements = 16384 u32 each
#define WSLOT 16384
__device__ uint32_t g_WH[8 * WSLOT];
__device__ uint32_t g_WL[8 * WSLOT];
// CSR build
__device__ int g_deg[NMAX];
__device__ int g_rowptr[NMAX];
__device__ int g_pos[NMAX];
__device__ int g_bsum[128];
__device__ int g_boff[128];
__device__ int g_eidx[EMAX];

__device__ __forceinline__ void red_add_v4(float* p, float4 v) {
    asm volatile("red.global.add.v4.f32 [%0], {%1, %2, %3, %4};"
                 :: "l"(p), "f"(v.x), "f"(v.y), "f"(v.z), "f"(v.w)
                 : "memory");
}

__device__ __forceinline__ uint32_t pack_bf16x2(float lo, float hi) {
    __nv_bfloat162 p = __floats2bfloat162_rn(lo, hi);  // .x = lo half
    uint32_t u;
    memcpy(&u, &p, 4);
    return u;
}

// ---------------- weight prep: split + transpose to [n][kpair] --------------
__global__ void k_prep_w(const float* __restrict__ W, int K, int N, int slot) {
    int idx = blockIdx.x * blockDim.x + threadIdx.x;   // n + N*kp (coalesced reads)
    int total = N * (K >> 1);
    if (idx >= total) return;
    int n = idx % N;
    int kp = idx / N;
    float v0 = W[(size_t)(2 * kp) * N + n];
    float v1 = W[(size_t)(2 * kp + 1) * N + n];
    float h0 = __bfloat162float(__float2bfloat16(v0));
    float h1 = __bfloat162float(__float2bfloat16(v1));
    size_t o = (size_t)slot * WSLOT + (size_t)n * (K >> 1) + kp;
    g_WH[o] = pack_bf16x2(h0, h1);
    g_WL[o] = pack_bf16x2(v0 - h0, v1 - h1);
}

// ---------------- CSR build ----------------

__global__ void k_zero_deg(int N) {
    int i = blockIdx.x * blockDim.x + threadIdx.x;
    if (i < N) g_deg[i] = 0;
}

__global__ void k_hist(const int* __restrict__ ei, int E) {
    int e = blockIdx.x * blockDim.x + threadIdx.x;
    if (e < E) atomicAdd(&g_deg[ei[(size_t)E + e]], 1);
}

__global__ void k_scan1(int N) {
    __shared__ int ts[256];
    int b = blockIdx.x, t = threadIdx.x;
    int base = b * 1024 + t * 4;
    int v0 = (base + 0 < N) ? g_deg[base + 0] : 0;
    int v1 = (base + 1 < N) ? g_deg[base + 1] : 0;
    int v2 = (base + 2 < N) ? g_deg[base + 2] : 0;
    int v3 = (base + 3 < N) ? g_deg[base + 3] : 0;
    int s = v0 + v1 + v2 + v3;
    ts[t] = s;
    __syncthreads();
    for (int off = 1; off < 256; off <<= 1) {
        int x = (t >= off) ? ts[t - off] : 0;
        __syncthreads();
        ts[t] += x;
        __syncthreads();
    }
    int excl = ts[t] - s;
    if (base + 0 < N) g_rowptr[base + 0] = excl; excl += v0;
    if (base + 1 < N) g_rowptr[base + 1] = excl; excl += v1;
    if (base + 2 < N) g_rowptr[base + 2] = excl; excl += v2;
    if (base + 3 < N) g_rowptr[base + 3] = excl;
    if (t == 255) g_bsum[b] = ts[255];
}

__global__ void k_scan2(int NB) {
    __shared__ int bs[128];
    int t = threadIdx.x;
    int v = (t < NB) ? g_bsum[t] : 0;
    bs[t] = v;
    __syncthreads();
    for (int off = 1; off < 128; off <<= 1) {
        int x = (t >= off) ? bs[t - off] : 0;
        __syncthreads();
        bs[t] += x;
        __syncthreads();
    }
    if (t < NB) g_boff[t] = bs[t] - v;
}

__global__ void k_scan3(int N) {
    int i = blockIdx.x * blockDim.x + threadIdx.x;
    if (i < N) {
        int r = g_rowptr[i] + g_boff[i >> 10];
        g_rowptr[i] = r;
        g_pos[i] = r;
    }
}

__global__ void k_fill(const int* __restrict__ ei, int E) {
    int e = blockIdx.x * blockDim.x + threadIdx.x;
    if (e >= E) return;
    int s = ei[e];
    int d = ei[(size_t)E + e];
    int p = atomicAdd(&g_pos[d], 1);
    g_eidx[p] = s;
}

// ---------------- per-layer kernels ----------------

__global__ void k_init_vf(const float* __restrict__ vn_emb) {
    int i = blockIdx.x * blockDim.x + threadIdx.x;
    if (i < NG * HD) g_vf[i] = vn_emb[i & (HD - 1)];
}

__global__ void k_compute_h(const float* __restrict__ src,
                            const int* __restrict__ batch,
                            int mode, int N) {
    int idx = blockIdx.x * blockDim.x + threadIdx.x;
    int total = N * (HD / 4);
    if (idx >= total) return;
    int row = idx >> 5;
    int c4  = (idx & 31) << 2;
    float4 v = *(const float4*)&src[(size_t)row * HD + c4];
    if (mode) {
        float4 a = *(const float4*)&g_bnA2[c4];
        float4 c = *(const float4*)&g_bnC2[c4];
        v.x = fmaxf(fmaf(v.x, a.x, c.x), 0.f);
        v.y = fmaxf(fmaf(v.y, a.y, c.y), 0.f);
        v.z = fmaxf(fmaf(v.z, a.z, c.z), 0.f);
        v.w = fmaxf(fmaf(v.w, a.w, c.w), 0.f);
        int g = batch[row];
        float4 u = *(const float4*)&g_vf[g * HD + c4];
        v.x += u.x; v.y += u.y; v.z += u.z; v.w += u.w;
    }
    *(float4*)&g_h[(size_t)row * HD + c4] = v;
}

// warp per node: z[n] = h[n] + sum_in h[src]
__global__ void k_gather(int N) {
    int warp = (blockIdx.x * blockDim.x + threadIdx.x) >> 5;
    int lane = threadIdx.x & 31;
    if (warp >= N) return;
    int c4 = lane * 4;
    float4 acc = *(const float4*)&g_h[(size_t)warp * HD + c4];
    int j = g_rowptr[warp];
    int end = j + g_deg[warp];
    for (; j + 4 <= end; j += 4) {
        int s0 = g_eidx[j], s1 = g_eidx[j + 1];
        int s2 = g_eidx[j + 2], s3 = g_eidx[j + 3];
        float4 a = *(const float4*)&g_h[(size_t)s0 * HD + c4];
        float4 b = *(const float4*)&g_h[(size_t)s1 * HD + c4];
        float4 c = *(const float4*)&g_h[(size_t)s2 * HD + c4];
        float4 d = *(const float4*)&g_h[(size_t)s3 * HD + c4];
        acc.x += a.x + b.x + c.x + d.x;
        acc.y += a.y + b.y + c.y + d.y;
        acc.z += a.z + b.z + c.z + d.z;
        acc.w += a.w + b.w + c.w + d.w;
    }
    for (; j < end; j++) {
        int s = g_eidx[j];
        float4 a = *(const float4*)&g_h[(size_t)s * HD + c4];
        acc.x += a.x; acc.y += a.y; acc.z += a.z; acc.w += a.w;
    }
    *(float4*)&g_agg[(size_t)warp * HD + c4] = acc;
}

// ---- split-BF16 GEMM (3 terms), double-buffered, pre-split weights --------
#define TBM 128
#define TBN 128
#define TBK 16
#define KP  9   // u32 stride per row (8 kpairs + 1 pad)

__global__ __launch_bounds__(256) void mma_gemm(
    const float* __restrict__ A,
    const uint32_t* __restrict__ WH, const uint32_t* __restrict__ WL,
    const float* __restrict__ bias, float* __restrict__ C,
    int M, int N, int K, int bnOnA)
{
    __shared__ uint32_t AsH[2][TBM][KP];
    __shared__ uint32_t AsL[2][TBM][KP];
    __shared__ uint32_t BsH[2][TBN][KP];
    __shared__ uint32_t BsL[2][TBN][KP];
    __shared__ float sSum[TBN], sSS[TBN];

    int tid = threadIdx.x;
    int lane = tid & 31;
    int warp = tid >> 5;
    int bRow = blockIdx.x * TBM;
    int bCol = blockIdx.y * TBN;
    int warpRow = (warp & 3) * 32;
    int warpCol = (warp >> 2) * 64;
    int Kp2 = K >> 1;

    if (tid < TBN) { sSum[tid] = 0.f; sSS[tid] = 0.f; }

    // A load coords
    int ar0 = tid >> 2,         ac0 = (tid & 3) << 2;
    int ar1 = (tid + 256) >> 2, ac1 = ((tid + 256) & 3) << 2;
    int gA0 = bRow + ar0, gA1 = bRow + ar1;
    // B load coords: thread -> (n, kpair-half)
    int nB = tid >> 1;
    int kpH = (tid & 1) << 2;   // 0 or 4

    float acc[2][8][4];
#pragma unroll
    for (int rt = 0; rt < 2; rt++)
#pragma unroll
        for (int ct = 0; ct < 8; ct++)
#pragma unroll
            for (int i = 0; i < 4; i++) acc[rt][ct][i] = 0.f;

    float4 aReg0, aReg1;
    uint4 bRegH, bRegL;
#define LOAD_TILE(kt)                                                         \
    do {                                                                      \
        int k0 = (kt) * TBK;                                                  \
        aReg0 = (gA0 < M) ? *(const float4*)&A[(size_t)gA0 * K + k0 + ac0]    \
                          : make_float4(0.f, 0.f, 0.f, 0.f);                  \
        aReg1 = (gA1 < M) ? *(const float4*)&A[(size_t)gA1 * K + k0 + ac1]    \
                          : make_float4(0.f, 0.f, 0.f, 0.f);                  \
        size_t wo = (size_t)(bCol + nB) * Kp2 + (kt) * 8 + kpH;               \
        bRegH = *(const uint4*)&WH[wo];                                       \
        bRegL = *(const uint4*)&WL[wo];                                       \
    } while (0)

    int nk = K / TBK;
    LOAD_TILE(0);

    for (int kt = 0; kt < nk; kt++) {
        int k0 = kt * TBK;
        int cur = kt & 1;

        // ---- stage A: bn + hi/lo bf16 split ----
        {
            float4 v = aReg0;
            if (bnOnA) {
                float4 ba = *(const float4*)&g_bnA[k0 + ac0];
                float4 bc = *(const float4*)&g_bnC[k0 + ac0];
                v.x = fmaxf(fmaf(v.x, ba.x, bc.x), 0.f);
                v.y = fmaxf(fmaf(v.y, ba.y, bc.y), 0.f);
                v.z = fmaxf(fmaf(v.z, ba.z, bc.z), 0.f);
                v.w = fmaxf(fmaf(v.w, ba.w, bc.w), 0.f);
            }
            float hx = __bfloat162float(__float2bfloat16(v.x));
            float hy = __bfloat162float(__float2bfloat16(v.y));
            float hz = __bfloat162float(__float2bfloat16(v.z));
            float hw = __bfloat162float(__float2bfloat16(v.w));
            AsH[cur][ar0][(ac0 >> 1) + 0] = pack_bf16x2(hx, hy);
            AsH[cur][ar0][(ac0 >> 1) + 1] = pack_bf16x2(hz, hw);
            AsL[cur][ar0][(ac0 >> 1) + 0] = pack_bf16x2(v.x - hx, v.y - hy);
            AsL[cur][ar0][(ac0 >> 1) + 1] = pack_bf16x2(v.z - hz, v.w - hw);

            v = aReg1;
            if (bnOnA) {
                float4 ba = *(const float4*)&g_bnA[k0 + ac1];
                float4 bc = *(const float4*)&g_bnC[k0 + ac1];
                v.x = fmaxf(fmaf(v.x, ba.x, bc.x), 0.f);
                v.y = fmaxf(fmaf(v.y, ba.y, bc.y), 0.f);
                v.z = fmaxf(fmaf(v.z, ba.z, bc.z), 0.f);
                v.w = fmaxf(fmaf(v.w, ba.w, bc.w), 0.f);
            }
            hx = __bfloat162float(__float2bfloat16(v.x));
            hy = __bfloat162float(__float2bfloat16(v.y));
            hz = __bfloat162float(__float2bfloat16(v.z));
            hw = __bfloat162float(__float2bfloat16(v.w));
            AsH[cur][ar1][(ac1 >> 1) + 0] = pack_bf16x2(hx, hy);
            AsH[cur][ar1][(ac1 >> 1) + 1] = pack_bf16x2(hz, hw);
            AsL[cur][ar1][(ac1 >> 1) + 0] = pack_bf16x2(v.x - hx, v.y - hy);
            AsL[cur][ar1][(ac1 >> 1) + 1] = pack_bf16x2(v.z - hz, v.w - hw);
        }
        // ---- stage B: plain u32 copies (pre-split, pre-transposed) ----
        BsH[cur][nB][kpH + 0] = bRegH.x;
        BsH[cur][nB][kpH + 1] = bRegH.y;
        BsH[cur][nB][kpH + 2] = bRegH.z;
        BsH[cur][nB][kpH + 3] = bRegH.w;
        BsL[cur][nB][kpH + 0] = bRegL.x;
        BsL[cur][nB][kpH + 1] = bRegL.y;
        BsL[cur][nB][kpH + 2] = bRegL.z;
        BsL[cur][nB][kpH + 3] = bRegL.w;
        __syncthreads();

        // ---- prefetch next tile into regs (hidden behind mma) ----
        if (kt + 1 < nk) LOAD_TILE(kt + 1);

        // ---- mma over stage cur ----
        int j = lane & 3;
        uint32_t aH[2][4], aL[2][4];
#pragma unroll
        for (int rt = 0; rt < 2; rt++) {
            int r = warpRow + rt * 16 + (lane >> 2);
            aH[rt][0] = AsH[cur][r][j];
            aH[rt][1] = AsH[cur][r + 8][j];
            aH[rt][2] = AsH[cur][r][j + 4];
            aH[rt][3] = AsH[cur][r + 8][j + 4];
            aL[rt][0] = AsL[cur][r][j];
            aL[rt][1] = AsL[cur][r + 8][j];
            aL[rt][2] = AsL[cur][r][j + 4];
            aL[rt][3] = AsL[cur][r + 8][j + 4];
        }
#pragma unroll
        for (int ct = 0; ct < 8; ct++) {
            int n = warpCol + ct * 8 + (lane >> 2);
            uint32_t bH0 = BsH[cur][n][j];
            uint32_t bH1 = BsH[cur][n][j + 4];
            uint32_t bL0 = BsL[cur][n][j];
            uint32_t bL1 = BsL[cur][n][j + 4];
#pragma unroll
            for (int rt = 0; rt < 2; rt++) {
#define MMA(A0,A1,A2,A3,B0,B1)                                                \
                asm volatile(                                                 \
                    "mma.sync.aligned.m16n8k16.row.col.f32.bf16.bf16.f32 "    \
                    "{%0,%1,%2,%3}, {%4,%5,%6,%7}, {%8,%9}, {%0,%1,%2,%3};"   \
                    : "+f"(acc[rt][ct][0]), "+f"(acc[rt][ct][1]),             \
                      "+f"(acc[rt][ct][2]), "+f"(acc[rt][ct][3])              \
                    : "r"(A0), "r"(A1), "r"(A2), "r"(A3),                     \
                      "r"(B0), "r"(B1))
                MMA(aL[rt][0], aL[rt][1], aL[rt][2], aL[rt][3], bH0, bH1);
                MMA(aH[rt][0], aH[rt][1], aH[rt][2], aH[rt][3], bL0, bL1);
                MMA(aH[rt][0], aH[rt][1], aH[rt][2], aH[rt][3], bH0, bH1);
#undef MMA
            }
        }
        __syncthreads();
    }
#undef LOAD_TILE

    // ---- epilogue: bias, store, fused column stats ----
#pragma unroll
    for (int ct = 0; ct < 8; ct++) {
        int j2 = warpCol + ct * 8 + 2 * (lane & 3);
        float b0v = __ldg(&bias[bCol + j2]);
        float b1v = __ldg(&bias[bCol + j2 + 1]);
#pragma unroll
        for (int rt = 0; rt < 2; rt++) {
            acc[rt][ct][0] += b0v; acc[rt][ct][1] += b1v;
            acc[rt][ct][2] += b0v; acc[rt][ct][3] += b1v;
        }
    }
#pragma unroll
    for (int rt = 0; rt < 2; rt++) {
        int r0 = bRow + warpRow + rt * 16 + (lane >> 2);
        int r1 = r0 + 8;
#pragma unroll
        for (int ct = 0; ct < 8; ct++) {
            int j2 = bCol + warpCol + ct * 8 + 2 * (lane & 3);
            if (r0 < M) *(float2*)&C[(size_t)r0 * N + j2] =
                make_float2(acc[rt][ct][0], acc[rt][ct][1]);
            if (r1 < M) *(float2*)&C[(size_t)r1 * N + j2] =
                make_float2(acc[rt][ct][2], acc[rt][ct][3]);
        }
    }
#pragma unroll
    for (int ct = 0; ct < 8; ct++) {
        float s0 = 0.f, q0 = 0.f, s1 = 0.f, q1 = 0.f;
#pragma unroll
        for (int rt = 0; rt < 2; rt++) {
            int r0 = bRow + warpRow + rt * 16 + (lane >> 2);
            int r1 = r0 + 8;
            if (r0 < M) {
                float v = acc[rt][ct][0]; s0 += v; q0 += v * v;
                v = acc[rt][ct][1]; s1 += v; q1 += v * v;
            }
            if (r1 < M) {
                float v = acc[rt][ct][2]; s0 += v; q0 += v * v;
                v = acc[rt][ct][3]; s1 += v; q1 += v * v;
            }
        }
#pragma unroll
        for (int m = 4; m < 32; m <<= 1) {
            s0 += __shfl_xor_sync(0xFFFFFFFF, s0, m);
            q0 += __shfl_xor_sync(0xFFFFFFFF, q0, m);
            s1 += __shfl_xor_sync(0xFFFFFFFF, s1, m);
            q1 += __shfl_xor_sync(0xFFFFFFFF, q1, m);
        }
        if ((lane >> 2) == 0) {
            int j2 = warpCol + ct * 8 + 2 * (lane & 3);
            atomicAdd(&sSum[j2], s0); atomicAdd(&sSS[j2], q0);
            atomicAdd(&sSum[j2 + 1], s1); atomicAdd(&sSS[j2 + 1], q1);
        }
    }
    __syncthreads();
    if (tid < TBN) {
        atomicAdd(&g_sum[bCol + tid], sSum[tid]);
        atomicAdd(&g_sumsq[bCol + tid], sSS[tid]);
    }
}

// reads stats, computes scale/shift, re-zeros stats for the next GEMM
__global__ void k_finalize(const float* __restrict__ gamma,
                           const float* __restrict__ beta,
                           int C, float invM,
                           float* __restrict__ outA, float* __restrict__ outC) {
    int t = threadIdx.x;
    if (t >= C) return;
    float mean = g_sum[t] * invM;
    float var = g_sumsq[t] * invM - mean * mean;
    float r = rsqrtf(var + EPS);
    float a = gamma[t] * r;
    outA[t] = a;
    outC[t] = beta[t] - mean * a;
    g_sum[t] = 0.f;
    g_sumsq[t] = 0.f;
}

__global__ void k_bn_act(const float* __restrict__ X, int M, int C, int doRelu,
                         const float* __restrict__ bnA, const float* __restrict__ bnC,
                         float* __restrict__ dst1) {
    int idx = blockIdx.x * blockDim.x + threadIdx.x;
    int total = M * C / 4;
    if (idx >= total) return;
    size_t off = (size_t)idx * 4;
    int col = (int)(off % C);
    float4 v = *(const float4*)&X[off];
    float4 a = *(const float4*)&bnA[col];
    float4 c = *(const float4*)&bnC[col];
    float4 y;
    y.x = fmaf(v.x, a.x, c.x);
    y.y = fmaf(v.y, a.y, c.y);
    y.z = fmaf(v.z, a.z, c.z);
    y.w = fmaf(v.w, a.w, c.w);
    if (doRelu) {
        y.x = fmaxf(y.x, 0.f); y.y = fmaxf(y.y, 0.f);
        y.z = fmaxf(y.z, 0.f); y.w = fmaxf(y.w, 0.f);
    }
    *(float4*)&dst1[off] = y;
}

__global__ void k_zero_pool() {
    int i = blockIdx.x * blockDim.x + threadIdx.x;
    if (i < NG * HD) g_pool[i] = 0.f;
    if (i < NG) g_cnt[i] = 0.f;
}

__global__ void k_pool_scatter(const float* __restrict__ X,
                               const int* __restrict__ batch,
                               int doRelu, int addCounts, int N) {
    int warp = (blockIdx.x * blockDim.x + threadIdx.x) >> 5;
    int lane = threadIdx.x & 31;
    if (warp >= N) return;
    int g = batch[warp];
    int c4 = lane * 4;
    float4 v = *(const float4*)&X[(size_t)warp * HD + c4];
    float4 a = *(const float4*)&g_bnA2[c4];
    float4 c = *(const float4*)&g_bnC2[c4];
    float4 y;
    y.x = fmaf(v.x, a.x, c.x);
    y.y = fmaf(v.y, a.y, c.y);
    y.z = fmaf(v.z, a.z, c.z);
    y.w = fmaf(v.w, a.w, c.w);
    if (doRelu) {
        y.x = fmaxf(y.x, 0.f); y.y = fmaxf(y.y, 0.f);
        y.z = fmaxf(y.z, 0.f); y.w = fmaxf(y.w, 0.f);
    }
    red_add_v4(&g_pool[g * HD + c4], y);
    if (addCounts && lane == 0) atomicAdd(&g_cnt[g], 1.f);
}

__global__ void k_vz() {
    int i = blockIdx.x * blockDim.x + threadIdx.x;
    if (i < NG * HD) g_vz[i] = g_pool[i] + g_vf[i];
}

__global__ void k_readout(float* __restrict__ out) {
    int i = blockIdx.x * blockDim.x + threadIdx.x;
    if (i < NG * HD) out[i] = g_pool[i] / fmaxf(g_cnt[i >> 7], 1.f);
}

__global__ void k_copy_vf(float* __restrict__ out) {
    int i = blockIdx.x * blockDim.x + threadIdx.x;
    if (i < NG * HD) out[i] = g_vf[i];
}

// ---------------- host ----------------
extern "C" void kernel_launch(void* const* d_in, const int* in_sizes, int n_in,
                              void* d_out, int out_size) {
    const float* x = (const float*)d_in[0];
    const int* ei = (const int*)d_in[1];
    const int* batch = (const int*)d_in[2];
    int base = 3;
    if (n_in > 3 && in_sizes[3] <= 2) base = 4;
    const float* conv_w1 = (const float*)d_in[base + 0];
    const float* conv_b1 = (const float*)d_in[base + 1];
    const float* conv_bn_g = (const float*)d_in[base + 2];
    const float* conv_bn_b = (const float*)d_in[base + 3];
    const float* conv_w2 = (const float*)d_in[base + 4];
    const float* conv_b2 = (const float*)d_in[base + 5];
    const float* bn_g = (const float*)d_in[base + 6];
    const float* bn_b = (const float*)d_in[base + 7];
    const float* vn_emb = (const float*)d_in[base + 8];
    const float* vw1 = (const float*)d_in[base + 9];
    const float* vb1 = (const float*)d_in[base + 10];
    const float* vbn1g = (const float*)d_in[base + 11];
    const float* vbn1b = (const float*)d_in[base + 12];
    const float* vw2 = (const float*)d_in[base + 13];
    const float* vb2 = (const float*)d_in[base + 14];
    const float* vbn2g = (const float*)d_in[base + 15];
    const float* vbn2b = (const float*)d_in[base + 16];

    int N = in_sizes[0] / HD;
    int E = in_sizes[1] / 2;
    float* out = (float*)d_out;

    float *p_agg, *p_t1, *p_t2, *p_vz, *p_vt1, *p_vt2, *p_vf;
    float *p_bnA, *p_bnC, *p_bnA2, *p_bnC2;
    uint32_t *p_WH, *p_WL;
    cudaGetSymbolAddress((void**)&p_agg, g_agg);
    cudaGetSymbolAddress((void**)&p_t1, g_t1);
    cudaGetSymbolAddress((void**)&p_t2, g_t2);
    cudaGetSymbolAddress((void**)&p_vz, g_vz);
    cudaGetSymbolAddress((void**)&p_vt1, g_vt1);
    cudaGetSymbolAddress((void**)&p_vt2, g_vt2);
    cudaGetSymbolAddress((void**)&p_vf, g_vf);
    cudaGetSymbolAddress((void**)&p_bnA, g_bnA);
    cudaGetSymbolAddress((void**)&p_bnC, g_bnC);
    cudaGetSymbolAddress((void**)&p_bnA2, g_bnA2);
    cudaGetSymbolAddress((void**)&p_bnC2, g_bnC2);
    cudaGetSymbolAddress((void**)&p_WH, g_WH);
    cudaGetSymbolAddress((void**)&p_WL, g_WL);

    int gN  = (N + 255) / 256;
    int gN4 = (N * (HD / 4) + 255) / 256;
    int gEt = (E + 255) / 256;
    int gNw = (N * 32 + 255) / 256;
    int gG = (NG * HD + 255) / 256;
    int gM = (N + TBM - 1) / TBM;
    int gV = (NG + TBM - 1) / TBM;
    int NB = (N + 1023) / 1024;
    int gW = (HD * HD2 / 2 + 255) / 256;   // 16384 threads per weight

    // ---- prep: split+transpose all weights once ----
    for (int i = 0; i < 3; i++) {
        k_prep_w<<<gW, 256>>>(conv_w1 + (size_t)i * HD * HD2, HD, HD2, i);
        k_prep_w<<<gW, 256>>>(conv_w2 + (size_t)i * HD2 * HD, HD2, HD, 3 + i);
    }
    k_prep_w<<<gW, 256>>>(vw1, HD, HD2, 6);
    k_prep_w<<<gW, 256>>>(vw2, HD2, HD, 7);

    // ---- build CSR once ----
    k_zero_deg<<<gN, 256>>>(N);
    k_hist<<<gEt, 256>>>(ei, E);
    k_scan1<<<NB, 256>>>(N);
    k_scan2<<<1, 128>>>(NB);
    k_scan3<<<gN, 256>>>(N);
    k_fill<<<gEt, 256>>>(ei, E);

    k_init_vf<<<gG, 256>>>(vn_emb);

    for (int i = 0; i < 3; i++) {
        const float* src = (i == 0) ? x : p_t2;
        k_compute_h<<<gN4, 256>>>(src, batch, i > 0 ? 1 : 0, N);
        k_gather<<<gNw, 256>>>(N);

        mma_gemm<<<dim3(gM, HD2 / TBN), 256>>>(
            p_agg, p_WH + (size_t)i * WSLOT, p_WL + (size_t)i * WSLOT,
            conv_b1 + i * HD2, p_t1, N, HD2, HD, 0);
        k_finalize<<<1, HD2>>>(conv_bn_g + i * HD2, conv_bn_b + i * HD2,
                               HD2, 1.0f / N, p_bnA, p_bnC);

        mma_gemm<<<dim3(gM, HD / TBN), 256>>>(
            p_t1, p_WH + (size_t)(3 + i) * WSLOT, p_WL + (size_t)(3 + i) * WSLOT,
            conv_b2 + i * HD, p_t2, N, HD, HD2, 1);
        k_finalize<<<1, HD>>>(bn_g + i * HD, bn_b + i * HD,
                              HD, 1.0f / N, p_bnA2, p_bnC2);

        if (i == 2) {
            k_bn_act<<<gN4, 256>>>(p_t2, N, HD, 0, p_bnA2, p_bnC2, out);
        }

        if (i == 1) {
            k_zero_pool<<<gG, 256>>>();
            k_pool_scatter<<<gNw, 256>>>(p_t2, batch, 1, 0, N);
            k_vz<<<gG, 256>>>();

            mma_gemm<<<dim3(gV, HD2 / TBN), 256>>>(
                p_vz, p_WH + (size_t)6 * WSLOT, p_WL + (size_t)6 * WSLOT,
                vb1, p_vt1, NG, HD2, HD, 0);
            k_finalize<<<1, HD2>>>(vbn1g, vbn1b, HD2, 1.0f / NG, p_bnA, p_bnC);

            mma_gemm<<<dim3(gV, HD / TBN), 256>>>(
                p_vt1, p_WH + (size_t)7 * WSLOT, p_WL + (size_t)7 * WSLOT,
                vb2, p_vt2, NG, HD, HD2, 1);
            k_finalize<<<1, HD>>>(vbn2g, vbn2b, HD, 1.0f / NG, p_bnA, p_bnC);
            k_bn_act<<<(NG * HD / 4 + 255) / 256, 256>>>(
                p_vt2, NG, HD, 1, p_bnA, p_bnC, p_vf);
        }
    }

    k_zero_pool<<<gG, 256>>>();
    k_pool_scatter<<<gNw, 256>>>(p_t2, batch, 0, 1, N);
    k_readout<<<gG, 256>>>(out + (size_t)N * HD);
    k_copy_vf<<<gG, 256>>>(out + (size_t)N * HD + NG * HD);
}

// round 13
// speedup vs baseline: 2.1787x; 1.0203x over previous
#include <cuda_runtime.h>
#include <cuda_bf16.h>
#include <cstdint>

#define HD   128
#define HD2  256
#define NMAX 100000
#define EMAX 1600000
#define NG   512
#define EPS  1e-5f

// ---------------- scratch (static device globals; no allocs) ----------------
__device__ float g_h[(size_t)NMAX * HD];
__device__ float g_agg[(size_t)NMAX * HD];
__device__ float g_t1[(size_t)NMAX * HD2];
__device__ float g_t2[(size_t)NMAX * HD];
__device__ float g_vf[NG * HD];
__device__ float g_vz[NG * HD];
__device__ float g_vt1[NG * HD2];
__device__ float g_vt2[NG * HD];
__device__ float g_pool[NG * HD];
__device__ float g_cnt[NG];
__device__ float g_sum[HD2];     // zero-init at load; k_finalize re-zeros after read
__device__ float g_sumsq[HD2];
__device__ float g_bnA[HD2];
__device__ float g_bnC[HD2];
__device__ float g_bnA2[HD];
__device__ float g_bnC2[HD];
// pre-split weights: hi/lo bf16 planes, [n][kpair] layout
#define WSLOT 16384
__device__ uint32_t g_WH[8 * WSLOT];
__device__ uint32_t g_WL[8 * WSLOT];
// CSR build
__device__ int g_deg[NMAX];
__device__ int g_rowptr[NMAX];
__device__ int g_pos[NMAX];
__device__ int g_bsum[128];
__device__ int g_boff[128];
__device__ int g_eidx[EMAX];

__device__ __forceinline__ void red_add_v4(float* p, float4 v) {
    asm volatile("red.global.add.v4.f32 [%0], {%1, %2, %3, %4};"
                 :: "l"(p), "f"(v.x), "f"(v.y), "f"(v.z), "f"(v.w)
                 : "memory");
}

__device__ __forceinline__ uint32_t pack_bf16x2(float lo, float hi) {
    __nv_bfloat162 p = __floats2bfloat162_rn(lo, hi);
    uint32_t u;
    memcpy(&u, &p, 4);
    return u;
}

// ---------------- weight prep: split + transpose to [n][kpair] --------------
__global__ void k_prep_w(const float* __restrict__ W, int K, int N, int slot) {
    int idx = blockIdx.x * blockDim.x + threadIdx.x;
    int total = N * (K >> 1);
    if (idx >= total) return;
    int n = idx % N;
    int kp = idx / N;
    float v0 = W[(size_t)(2 * kp) * N + n];
    float v1 = W[(size_t)(2 * kp + 1) * N + n];
    float h0 = __bfloat162float(__float2bfloat16(v0));
    float h1 = __bfloat162float(__float2bfloat16(v1));
    size_t o = (size_t)slot * WSLOT + (size_t)n * (K >> 1) + kp;
    g_WH[o] = pack_bf16x2(h0, h1);
    g_WL[o] = pack_bf16x2(v0 - h0, v1 - h1);
}

// ---------------- CSR build ----------------

__global__ void k_zero_deg(int N) {
    int i = blockIdx.x * blockDim.x + threadIdx.x;
    if (i < N) g_deg[i] = 0;
}

__global__ void k_hist(const int* __restrict__ ei, int E) {
    int e = blockIdx.x * blockDim.x + threadIdx.x;
    if (e < E) atomicAdd(&g_deg[ei[(size_t)E + e]], 1);
}

__global__ void k_scan1(int N) {
    __shared__ int ts[256];
    int b = blockIdx.x, t = threadIdx.x;
    int base = b * 1024 + t * 4;
    int v0 = (base + 0 < N) ? g_deg[base + 0] : 0;
    int v1 = (base + 1 < N) ? g_deg[base + 1] : 0;
    int v2 = (base + 2 < N) ? g_deg[base + 2] : 0;
    int v3 = (base + 3 < N) ? g_deg[base + 3] : 0;
    int s = v0 + v1 + v2 + v3;
    ts[t] = s;
    __syncthreads();
    for (int off = 1; off < 256; off <<= 1) {
        int x = (t >= off) ? ts[t - off] : 0;
        __syncthreads();
        ts[t] += x;
        __syncthreads();
    }
    int excl = ts[t] - s;
    if (base + 0 < N) g_rowptr[base + 0] = excl; excl += v0;
    if (base + 1 < N) g_rowptr[base + 1] = excl; excl += v1;
    if (base + 2 < N) g_rowptr[base + 2] = excl; excl += v2;
    if (base + 3 < N) g_rowptr[base + 3] = excl;
    if (t == 255) g_bsum[b] = ts[255];
}

__global__ void k_scan2(int NB) {
    __shared__ int bs[128];
    int t = threadIdx.x;
    int v = (t < NB) ? g_bsum[t] : 0;
    bs[t] = v;
    __syncthreads();
    for (int off = 1; off < 128; off <<= 1) {
        int x = (t >= off) ? bs[t - off] : 0;
        __syncthreads();
        bs[t] += x;
        __syncthreads();
    }
    if (t < NB) g_boff[t] = bs[t] - v;
}

__global__ void k_scan3(int N) {
    int i = blockIdx.x * blockDim.x + threadIdx.x;
    if (i < N) {
        int r = g_rowptr[i] + g_boff[i >> 10];
        g_rowptr[i] = r;
        g_pos[i] = r;
    }
}

__global__ void k_fill(const int* __restrict__ ei, int E) {
    int e = blockIdx.x * blockDim.x + threadIdx.x;
    if (e >= E) return;
    int s = ei[e];
    int d = ei[(size_t)E + e];
    int p = atomicAdd(&g_pos[d], 1);
    g_eidx[p] = s;
}

// ---------------- per-layer kernels ----------------

__global__ void k_init_vf(const float* __restrict__ vn_emb) {
    int i = blockIdx.x * blockDim.x + threadIdx.x;
    if (i < NG * HD) g_vf[i] = vn_emb[i & (HD - 1)];
}

// h = relu(src*bnA2+bnC2) + vf[batch]   (layers > 0 only)
__global__ void k_compute_h(const float* __restrict__ src,
                            const int* __restrict__ batch, int N) {
    int idx = blockIdx.x * blockDim.x + threadIdx.x;
    int total = N * (HD / 4);
    if (idx >= total) return;
    int row = idx >> 5;
    int c4  = (idx & 31) << 2;
    float4 v = *(const float4*)&src[(size_t)row * HD + c4];
    float4 a = *(const float4*)&g_bnA2[c4];
    float4 c = *(const float4*)&g_bnC2[c4];
    v.x = fmaxf(fmaf(v.x, a.x, c.x), 0.f);
    v.y = fmaxf(fmaf(v.y, a.y, c.y), 0.f);
    v.z = fmaxf(fmaf(v.z, a.z, c.z), 0.f);
    v.w = fmaxf(fmaf(v.w, a.w, c.w), 0.f);
    int g = batch[row];
    float4 u = *(const float4*)&g_vf[g * HD + c4];
    v.x += u.x; v.y += u.y; v.z += u.z; v.w += u.w;
    *(float4*)&g_h[(size_t)row * HD + c4] = v;
}

// warp per node: z[n] = hsrc[n] + sum_in hsrc[src]
__global__ void k_gather(const float* __restrict__ hsrc, int N) {
    int warp = (blockIdx.x * blockDim.x + threadIdx.x) >> 5;
    int lane = threadIdx.x & 31;
    if (warp >= N) return;
    int c4 = lane * 4;
    float4 acc = *(const float4*)&hsrc[(size_t)warp * HD + c4];
    int j = g_rowptr[warp];
    int end = j + g_deg[warp];
    for (; j + 4 <= end; j += 4) {
        int s0 = g_eidx[j], s1 = g_eidx[j + 1];
        int s2 = g_eidx[j + 2], s3 = g_eidx[j + 3];
        float4 a = *(const float4*)&hsrc[(size_t)s0 * HD + c4];
        float4 b = *(const float4*)&hsrc[(size_t)s1 * HD + c4];
        float4 c = *(const float4*)&hsrc[(size_t)s2 * HD + c4];
        float4 d = *(const float4*)&hsrc[(size_t)s3 * HD + c4];
        acc.x += a.x + b.x + c.x + d.x;
        acc.y += a.y + b.y + c.y + d.y;
        acc.z += a.z + b.z + c.z + d.z;
        acc.w += a.w + b.w + c.w + d.w;
    }
    for (; j < end; j++) {
        int s = g_eidx[j];
        float4 a = *(const float4*)&hsrc[(size_t)s * HD + c4];
        acc.x += a.x; acc.y += a.y; acc.z += a.z; acc.w += a.w;
    }
    *(float4*)&g_agg[(size_t)warp * HD + c4] = acc;
}

// ---- split-BF16 GEMM (3 terms), double-buffered, pre-split weights --------
#define TBM 128
#define TBN 128
#define TBK 16
#define KP  9   // u32 stride per row (8 kpairs + 1 pad)

__global__ __launch_bounds__(256) void mma_gemm(
    const float* __restrict__ A,
    const uint32_t* __restrict__ WH, const uint32_t* __restrict__ WL,
    const float* __restrict__ bias, float* __restrict__ C,
    int M, int N, int K, int bnOnA)
{
    __shared__ uint32_t AsH[2][TBM][KP];
    __shared__ uint32_t AsL[2][TBM][KP];
    __shared__ uint32_t BsH[2][TBN][KP];
    __shared__ uint32_t BsL[2][TBN][KP];
    __shared__ float sSum[TBN], sSS[TBN];

    int tid = threadIdx.x;
    int lane = tid & 31;
    int warp = tid >> 5;
    int bRow = blockIdx.x * TBM;
    int bCol = blockIdx.y * TBN;
    int warpRow = (warp & 3) * 32;
    int warpCol = (warp >> 2) * 64;
    int Kp2 = K >> 1;

    if (tid < TBN) { sSum[tid] = 0.f; sSS[tid] = 0.f; }

    int ar0 = tid >> 2,         ac0 = (tid & 3) << 2;
    int ar1 = (tid + 256) >> 2, ac1 = ((tid + 256) & 3) << 2;
    int gA0 = bRow + ar0, gA1 = bRow + ar1;
    int nB = tid >> 1;
    int kpH = (tid & 1) << 2;

    float acc[2][8][4];
#pragma unroll
    for (int rt = 0; rt < 2; rt++)
#pragma unroll
        for (int ct = 0; ct < 8; ct++)
#pragma unroll
            for (int i = 0; i < 4; i++) acc[rt][ct][i] = 0.f;

    float4 aReg0, aReg1;
    uint4 bRegH, bRegL;
#define LOAD_TILE(kt)                                                         \
    do {                                                                      \
        int k0 = (kt) * TBK;                                                  \
        aReg0 = (gA0 < M) ? *(const float4*)&A[(size_t)gA0 * K + k0 + ac0]    \
                          : make_float4(0.f, 0.f, 0.f, 0.f);                  \
        aReg1 = (gA1 < M) ? *(const float4*)&A[(size_t)gA1 * K + k0 + ac1]    \
                          : make_float4(0.f, 0.f, 0.f, 0.f);                  \
        size_t wo = (size_t)(bCol + nB) * Kp2 + (kt) * 8 + kpH;               \
        bRegH = *(const uint4*)&WH[wo];                                       \
        bRegL = *(const uint4*)&WL[wo];                                       \
    } while (0)

    int nk = K / TBK;
    LOAD_TILE(0);

    for (int kt = 0; kt < nk; kt++) {
        int k0 = kt * TBK;
        int cur = kt & 1;

        {
            float4 v = aReg0;
            if (bnOnA) {
                float4 ba = *(const float4*)&g_bnA[k0 + ac0];
                float4 bc = *(const float4*)&g_bnC[k0 + ac0];
                v.x = fmaxf(fmaf(v.x, ba.x, bc.x), 0.f);
                v.y = fmaxf(fmaf(v.y, ba.y, bc.y), 0.f);
                v.z = fmaxf(fmaf(v.z, ba.z, bc.z), 0.f);
                v.w = fmaxf(fmaf(v.w, ba.w, bc.w), 0.f);
            }
            float hx = __bfloat162float(__float2bfloat16(v.x));
            float hy = __bfloat162float(__float2bfloat16(v.y));
            float hz = __bfloat162float(__float2bfloat16(v.z));
            float hw = __bfloat162float(__float2bfloat16(v.w));
            AsH[cur][ar0][(ac0 >> 1) + 0] = pack_bf16x2(hx, hy);
            AsH[cur][ar0][(ac0 >> 1) + 1] = pack_bf16x2(hz, hw);
            AsL[cur][ar0][(ac0 >> 1) + 0] = pack_bf16x2(v.x - hx, v.y - hy);
            AsL[cur][ar0][(ac0 >> 1) + 1] = pack_bf16x2(v.z - hz, v.w - hw);

            v = aReg1;
            if (bnOnA) {
                float4 ba = *(const float4*)&g_bnA[k0 + ac1];
                float4 bc = *(const float4*)&g_bnC[k0 + ac1];
                v.x = fmaxf(fmaf(v.x, ba.x, bc.x), 0.f);
                v.y = fmaxf(fmaf(v.y, ba.y, bc.y), 0.f);
                v.z = fmaxf(fmaf(v.z, ba.z, bc.z), 0.f);
                v.w = fmaxf(fmaf(v.w, ba.w, bc.w), 0.f);
            }
            hx = __bfloat162float(__float2bfloat16(v.x));
            hy = __bfloat162float(__float2bfloat16(v.y));
            hz = __bfloat162float(__float2bfloat16(v.z));
            hw = __bfloat162float(__float2bfloat16(v.w));
            AsH[cur][ar1][(ac1 >> 1) + 0] = pack_bf16x2(hx, hy);
            AsH[cur][ar1][(ac1 >> 1) + 1] = pack_bf16x2(hz, hw);
            AsL[cur][ar1][(ac1 >> 1) + 0] = pack_bf16x2(v.x - hx, v.y - hy);
            AsL[cur][ar1][(ac1 >> 1) + 1] = pack_bf16x2(v.z - hz, v.w - hw);
        }
        BsH[cur][nB][kpH + 0] = bRegH.x;
        BsH[cur][nB][kpH + 1] = bRegH.y;
        BsH[cur][nB][kpH + 2] = bRegH.z;
        BsH[cur][nB][kpH + 3] = bRegH.w;
        BsL[cur][nB][kpH + 0] = bRegL.x;
        BsL[cur][nB][kpH + 1] = bRegL.y;
        BsL[cur][nB][kpH + 2] = bRegL.z;
        BsL[cur][nB][kpH + 3] = bRegL.w;
        __syncthreads();

        if (kt + 1 < nk) LOAD_TILE(kt + 1);

        int j = lane & 3;
        uint32_t aH[2][4], aL[2][4];
#pragma unroll
        for (int rt = 0; rt < 2; rt++) {
            int r = warpRow + rt * 16 + (lane >> 2);
            aH[rt][0] = AsH[cur][r][j];
            aH[rt][1] = AsH[cur][r + 8][j];
            aH[rt][2] = AsH[cur][r][j + 4];
            aH[rt][3] = AsH[cur][r + 8][j + 4];
            aL[rt][0] = AsL[cur][r][j];
            aL[rt][1] = AsL[cur][r + 8][j];
            aL[rt][2] = AsL[cur][r][j + 4];
            aL[rt][3] = AsL[cur][r + 8][j + 4];
        }
#pragma unroll
        for (int ct = 0; ct < 8; ct++) {
            int n = warpCol + ct * 8 + (lane >> 2);
            uint32_t bH0 = BsH[cur][n][j];
            uint32_t bH1 = BsH[cur][n][j + 4];
            uint32_t bL0 = BsL[cur][n][j];
            uint32_t bL1 = BsL[cur][n][j + 4];
#pragma unroll
            for (int rt = 0; rt < 2; rt++) {
#define MMA(A0,A1,A2,A3,B0,B1)                                                \
                asm volatile(                                                 \
                    "mma.sync.aligned.m16n8k16.row.col.f32.bf16.bf16.f32 "    \
                    "{%0,%1,%2,%3}, {%4,%5,%6,%7}, {%8,%9}, {%0,%1,%2,%3};"   \
                    : "+f"(acc[rt][ct][0]), "+f"(acc[rt][ct][1]),             \
                      "+f"(acc[rt][ct][2]), "+f"(acc[rt][ct][3])              \
                    : "r"(A0), "r"(A1), "r"(A2), "r"(A3),                     \
                      "r"(B0), "r"(B1))
                MMA(aL[rt][0], aL[rt][1], aL[rt][2], aL[rt][3], bH0, bH1);
                MMA(aH[rt][0], aH[rt][1], aH[rt][2], aH[rt][3], bL0, bL1);
                MMA(aH[rt][0], aH[rt][1], aH[rt][2], aH[rt][3], bH0, bH1);
#undef MMA
            }
        }
        __syncthreads();
    }
#undef LOAD_TILE

    // ---- epilogue: bias, store, fused column stats ----
#pragma unroll
    for (int ct = 0; ct < 8; ct++) {
        int j2 = warpCol + ct * 8 + 2 * (lane & 3);
        float b0v = __ldg(&bias[bCol + j2]);
        float b1v = __ldg(&bias[bCol + j2 + 1]);
#pragma unroll
        for (int rt = 0; rt < 2; rt++) {
            acc[rt][ct][0] += b0v; acc[rt][ct][1] += b1v;
            acc[rt][ct][2] += b0v; acc[rt][ct][3] += b1v;
        }
    }
#pragma unroll
    for (int rt = 0; rt < 2; rt++) {
        int r0 = bRow + warpRow + rt * 16 + (lane >> 2);
        int r1 = r0 + 8;
#pragma unroll
        for (int ct = 0; ct < 8; ct++) {
            int j2 = bCol + warpCol + ct * 8 + 2 * (lane & 3);
            if (r0 < M) *(float2*)&C[(size_t)r0 * N + j2] =
                make_float2(acc[rt][ct][0], acc[rt][ct][1]);
            if (r1 < M) *(float2*)&C[(size_t)r1 * N + j2] =
                make_float2(acc[rt][ct][2], acc[rt][ct][3]);
        }
    }
#pragma unroll
    for (int ct = 0; ct < 8; ct++) {
        float s0 = 0.f, q0 = 0.f, s1 = 0.f, q1 = 0.f;
#pragma unroll
        for (int rt = 0; rt < 2; rt++) {
            int r0 = bRow + warpRow + rt * 16 + (lane >> 2);
            int r1 = r0 + 8;
            if (r0 < M) {
                float v = acc[rt][ct][0]; s0 += v; q0 += v * v;
                v = acc[rt][ct][1]; s1 += v; q1 += v * v;
            }
            if (r1 < M) {
                float v = acc[rt][ct][2]; s0 += v; q0 += v * v;
                v = acc[rt][ct][3]; s1 += v; q1 += v * v;
            }
        }
#pragma unroll
        for (int m = 4; m < 32; m <<= 1) {
            s0 += __shfl_xor_sync(0xFFFFFFFF, s0, m);
            q0 += __shfl_xor_sync(0xFFFFFFFF, q0, m);
            s1 += __shfl_xor_sync(0xFFFFFFFF, s1, m);
            q1 += __shfl_xor_sync(0xFFFFFFFF, q1, m);
        }
        if ((lane >> 2) == 0) {
            int j2 = warpCol + ct * 8 + 2 * (lane & 3);
            atomicAdd(&sSum[j2], s0); atomicAdd(&sSS[j2], q0);
            atomicAdd(&sSum[j2 + 1], s1); atomicAdd(&sSS[j2 + 1], q1);
        }
    }
    __syncthreads();
    if (tid < TBN) {
        atomicAdd(&g_sum[bCol + tid], sSum[tid]);
        atomicAdd(&g_sumsq[bCol + tid], sSS[tid]);
    }
}

// reads stats, computes scale/shift, re-zeros stats for the next GEMM
__global__ void k_finalize(const float* __restrict__ gamma,
                           const float* __restrict__ beta,
                           int C, float invM,
                           float* __restrict__ outA, float* __restrict__ outC) {
    int t = threadIdx.x;
    if (t >= C) return;
    float mean = g_sum[t] * invM;
    float var = g_sumsq[t] * invM - mean * mean;
    float r = rsqrtf(var + EPS);
    float a = gamma[t] * r;
    outA[t] = a;
    outC[t] = beta[t] - mean * a;
    g_sum[t] = 0.f;
    g_sumsq[t] = 0.f;
}

__global__ void k_bn_act(const float* __restrict__ X, int M, int C, int doRelu,
                         const float* __restrict__ bnA, const float* __restrict__ bnC,
                         float* __restrict__ dst1) {
    int idx = blockIdx.x * blockDim.x + threadIdx.x;
    int total = M * C / 4;
    if (idx >= total) return;
    size_t off = (size_t)idx * 4;
    int col = (int)(off % C);
    float4 v = *(const float4*)&X[off];
    float4 a = *(const float4*)&bnA[col];
    float4 c = *(const float4*)&bnC[col];
    float4 y;
    y.x = fmaf(v.x, a.x, c.x);
    y.y = fmaf(v.y, a.y, c.y);
    y.z = fmaf(v.z, a.z, c.z);
    y.w = fmaf(v.w, a.w, c.w);
    if (doRelu) {
        y.x = fmaxf(y.x, 0.f); y.y = fmaxf(y.y, 0.f);
        y.z = fmaxf(y.z, 0.f); y.w = fmaxf(y.w, 0.f);
    }
    *(float4*)&dst1[off] = y;
}

__global__ void k_zero_pool() {
    int i = blockIdx.x * blockDim.x + threadIdx.x;
    if (i < NG * HD) g_pool[i] = 0.f;
    if (i < NG) g_cnt[i] = 0.f;
}

// layer-1 virtual-node pool: pool += relu(bn2(X)); no counts
__global__ void k_pool_scatter(const float* __restrict__ X,
                               const int* __restrict__ batch, int N) {
    int warp = (blockIdx.x * blockDim.x + threadIdx.x) >> 5;
    int lane = threadIdx.x & 31;
    if (warp >= N) return;
    int g = batch[warp];
    int c4 = lane * 4;
    float4 v = *(const float4*)&X[(size_t)warp * HD + c4];
    float4 a = *(const float4*)&g_bnA2[c4];
    float4 c = *(const float4*)&g_bnC2[c4];
    float4 y;
    y.x = fmaxf(fmaf(v.x, a.x, c.x), 0.f);
    y.y = fmaxf(fmaf(v.y, a.y, c.y), 0.f);
    y.z = fmaxf(fmaf(v.z, a.z, c.z), 0.f);
    y.w = fmaxf(fmaf(v.w, a.w, c.w), 0.f);
    red_add_v4(&g_pool[g * HD + c4], y);
}

// final fused: out = bn2(X) (no relu); pool += out rows; counts
__global__ void k_out_pool(const float* __restrict__ X,
                           const int* __restrict__ batch,
                           float* __restrict__ out, int N) {
    int warp = (blockIdx.x * blockDim.x + threadIdx.x) >> 5;
    int lane = threadIdx.x & 31;
    if (warp >= N) return;
    int g = batch[warp];
    int c4 = lane * 4;
    float4 v = *(const float4*)&X[(size_t)warp * HD + c4];
    float4 a = *(const float4*)&g_bnA2[c4];
    float4 c = *(const float4*)&g_bnC2[c4];
    float4 y;
    y.x = fmaf(v.x, a.x, c.x);
    y.y = fmaf(v.y, a.y, c.y);
    y.z = fmaf(v.z, a.z, c.z);
    y.w = fmaf(v.w, a.w, c.w);
    *(float4*)&out[(size_t)warp * HD + c4] = y;
    red_add_v4(&g_pool[g * HD + c4], y);
    if (lane == 0) atomicAdd(&g_cnt[g], 1.f);
}

__global__ void k_vz() {
    int i = blockIdx.x * blockDim.x + threadIdx.x;
    if (i < NG * HD) g_vz[i] = g_pool[i] + g_vf[i];
}

// readout + vf copy fused (both NG*HD)
__global__ void k_readout_vf(float* __restrict__ outR, float* __restrict__ outV) {
    int i = blockIdx.x * blockDim.x + threadIdx.x;
    if (i < NG * HD) {
        outR[i] = g_pool[i] / fmaxf(g_cnt[i >> 7], 1.f);
        outV[i] = g_vf[i];
    }
}

// ---------------- host ----------------
extern "C" void kernel_launch(void* const* d_in, const int* in_sizes, int n_in,
                              void* d_out, int out_size) {
    const float* x = (const float*)d_in[0];
    const int* ei = (const int*)d_in[1];
    const int* batch = (const int*)d_in[2];
    int base = 3;
    if (n_in > 3 && in_sizes[3] <= 2) base = 4;
    const float* conv_w1 = (const float*)d_in[base + 0];
    const float* conv_b1 = (const float*)d_in[base + 1];
    const float* conv_bn_g = (const float*)d_in[base + 2];
    const float* conv_bn_b = (const float*)d_in[base + 3];
    const float* conv_w2 = (const float*)d_in[base + 4];
    const float* conv_b2 = (const float*)d_in[base + 5];
    const float* bn_g = (const float*)d_in[base + 6];
    const float* bn_b = (const float*)d_in[base + 7];
    const float* vn_emb = (const float*)d_in[base + 8];
    const float* vw1 = (const float*)d_in[base + 9];
    const float* vb1 = (const float*)d_in[base + 10];
    const float* vbn1g = (const float*)d_in[base + 11];
    const float* vbn1b = (const float*)d_in[base + 12];
    const float* vw2 = (const float*)d_in[base + 13];
    const float* vb2 = (const float*)d_in[base + 14];
    const float* vbn2g = (const float*)d_in[base + 15];
    const float* vbn2b = (const float*)d_in[base + 16];

    int N = in_sizes[0] / HD;
    int E = in_sizes[1] / 2;
    float* out = (float*)d_out;

    float *p_h, *p_agg, *p_t1, *p_t2, *p_vz, *p_vt1, *p_vt2, *p_vf;
    float *p_bnA, *p_bnC, *p_bnA2, *p_bnC2;
    uint32_t *p_WH, *p_WL;
    cudaGetSymbolAddress((void**)&p_h, g_h);
    cudaGetSymbolAddress((void**)&p_agg, g_agg);
    cudaGetSymbolAddress((void**)&p_t1, g_t1);
    cudaGetSymbolAddress((void**)&p_t2, g_t2);
    cudaGetSymbolAddress((void**)&p_vz, g_vz);
    cudaGetSymbolAddress((void**)&p_vt1, g_vt1);
    cudaGetSymbolAddress((void**)&p_vt2, g_vt2);
    cudaGetSymbolAddress((void**)&p_vf, g_vf);
    cudaGetSymbolAddress((void**)&p_bnA, g_bnA);
    cudaGetSymbolAddress((void**)&p_bnC, g_bnC);
    cudaGetSymbolAddress((void**)&p_bnA2, g_bnA2);
    cudaGetSymbolAddress((void**)&p_bnC2, g_bnC2);
    cudaGetSymbolAddress((void**)&p_WH, g_WH);
    cudaGetSymbolAddress((void**)&p_WL, g_WL);

    int gN  = (N + 255) / 256;
    int gN4 = (N * (HD / 4) + 255) / 256;
    int gEt = (E + 255) / 256;
    int gNw = (N * 32 + 255) / 256;
    int gG = (NG * HD + 255) / 256;
    int gM = (N + TBM - 1) / TBM;
    int gV = (NG + TBM - 1) / TBM;
    int NB = (N + 1023) / 1024;
    int gW = (HD * HD2 / 2 + 255) / 256;

    // ---- prep: split+transpose all weights once ----
    for (int i = 0; i < 3; i++) {
        k_prep_w<<<gW, 256>>>(conv_w1 + (size_t)i * HD * HD2, HD, HD2, i);
        k_prep_w<<<gW, 256>>>(conv_w2 + (size_t)i * HD2 * HD, HD2, HD, 3 + i);
    }
    k_prep_w<<<gW, 256>>>(vw1, HD, HD2, 6);
    k_prep_w<<<gW, 256>>>(vw2, HD2, HD, 7);

    // ---- build CSR once ----
    k_zero_deg<<<gN, 256>>>(N);
    k_hist<<<gEt, 256>>>(ei, E);
    k_scan1<<<NB, 256>>>(N);
    k_scan2<<<1, 128>>>(NB);
    k_scan3<<<gN, 256>>>(N);
    k_fill<<<gEt, 256>>>(ei, E);

    k_init_vf<<<gG, 256>>>(vn_emb);

    for (int i = 0; i < 3; i++) {
        const float* hsrc;
        if (i == 0) {
            hsrc = x;                                   // h == x; no copy pass
        } else {
            k_compute_h<<<gN4, 256>>>(p_t2, batch, N);  // h = relu(bn2(t2))+vf
            hsrc = p_h;
        }
        k_gather<<<gNw, 256>>>(hsrc, N);

        mma_gemm<<<dim3(gM, HD2 / TBN), 256>>>(
            p_agg, p_WH + (size_t)i * WSLOT, p_WL + (size_t)i * WSLOT,
            conv_b1 + i * HD2, p_t1, N, HD2, HD, 0);
        k_finalize<<<1, HD2>>>(conv_bn_g + i * HD2, conv_bn_b + i * HD2,
                               HD2, 1.0f / N, p_bnA, p_bnC);

        mma_gemm<<<dim3(gM, HD / TBN), 256>>>(
            p_t1, p_WH + (size_t)(3 + i) * WSLOT, p_WL + (size_t)(3 + i) * WSLOT,
            conv_b2 + i * HD, p_t2, N, HD, HD2, 1);
        k_finalize<<<1, HD>>>(bn_g + i * HD, bn_b + i * HD,
                              HD, 1.0f / N, p_bnA2, p_bnC2);

        if (i == 1) {
            k_zero_pool<<<gG, 256>>>();
            k_pool_scatter<<<gNw, 256>>>(p_t2, batch, N);
            k_vz<<<gG, 256>>>();

            mma_gemm<<<dim3(gV, HD2 / TBN), 256>>>(
                p_vz, p_WH + (size_t)6 * WSLOT, p_WL + (size_t)6 * WSLOT,
                vb1, p_vt1, NG, HD2, HD, 0);
            k_finalize<<<1, HD2>>>(vbn1g, vbn1b, HD2, 1.0f / NG, p_bnA, p_bnC);

            mma_gemm<<<dim3(gV, HD / TBN), 256>>>(
                p_vt1, p_WH + (size_t)7 * WSLOT, p_WL + (size_t)7 * WSLOT,
                vb2, p_vt2, NG, HD, HD2, 1);
            k_finalize<<<1, HD>>>(vbn2g, vbn2b, HD, 1.0f / NG, p_bnA, p_bnC);
            k_bn_act<<<(NG * HD / 4 + 255) / 256, 256>>>(
                p_vt2, NG, HD, 1, p_bnA, p_bnC, p_vf);
        }
    }

    // final: fused out-write + mean-pool (+counts), then readout + vf copy
    k_zero_pool<<<gG, 256>>>();
    k_out_pool<<<gNw, 256>>>(p_t2, batch, out, N);
    k_readout_vf<<<gG, 256>>>(out + (size_t)N * HD,
                              out + (size_t)N * HD + NG * HD);
}